// round 5
// baseline (speedup 1.0000x reference)
#include <cuda_runtime.h>
#include <cuda_fp16.h>
#include <math.h>
#include <stdint.h>

#define NN 50000
#define EE 800000
#define DIM 128
#define HC 256        // HEADS*DIM
#define DMLP 512

// ---------------- scratch (device globals; no allocation) ----------------
__device__ float  g_x   [NN * DIM];
__device__ float  g_h   [NN * DIM];
__device__ __half g_xlh [NN * HC];     // fp16 source transform
__device__ __half g_xrh [NN * HC];     // fp16 target transform
__device__ float  g_agg [NN * HC];
__device__ float  g_mlp [NN * DMLP];
__device__ float  g_s   [EE * 2];
__device__ float  g_ex  [EE * 2];
__device__ float  g_smax[NN * 2];
__device__ float  g_den [NN * 2];
__device__ float  g_bpe [DIM];

// ---------------- helpers ----------------
__device__ __forceinline__ float lrelu(float v) { return v > 0.f ? v : 0.2f * v; }

__device__ __forceinline__ void atomicMaxF(float* addr, float v) {
    if (v >= 0.f) atomicMax((int*)addr, __float_as_int(v));
    else          atomicMin((unsigned int*)addr, __float_as_uint(v));
}

__device__ __forceinline__ void red4(float* p, float a, float b, float c, float d) {
    asm volatile("red.global.add.v4.f32 [%0], {%1,%2,%3,%4};"
                 :: "l"(p), "f"(a), "f"(b), "f"(c), "f"(d) : "memory");
}

__device__ __forceinline__ uint32_t smem_u32(const void* p) {
    return (uint32_t)__cvta_generic_to_shared(p);
}

#define CP_ASYNC16(dst, src, szbytes) \
    asm volatile("cp.async.cg.shared.global [%0], [%1], 16, %2;" \
                 :: "r"(dst), "l"(src), "r"(szbytes))
#define CP_COMMIT()  asm volatile("cp.async.commit_group;")
#define CP_WAIT0()   asm volatile("cp.async.wait_group 0;")

// ---------------- layernorm: warp per row ----------------
__global__ void ln_kernel(const float* __restrict__ x, const float* __restrict__ g,
                          const float* __restrict__ b, float* __restrict__ out, int n)
{
    int warp = (blockIdx.x * blockDim.x + threadIdx.x) >> 5;
    int lane = threadIdx.x & 31;
    if (warp >= n) return;
    const float4 v = ((const float4*)(x + (size_t)warp * DIM))[lane];
    float s = v.x + v.y + v.z + v.w;
    #pragma unroll
    for (int o = 16; o; o >>= 1) s += __shfl_xor_sync(~0u, s, o);
    float mu = s * (1.f / 128.f);
    float dx = v.x - mu, dy = v.y - mu, dz = v.z - mu, dw = v.w - mu;
    float q = dx*dx + dy*dy + dz*dz + dw*dw;
    #pragma unroll
    for (int o = 16; o; o >>= 1) q += __shfl_xor_sync(~0u, q, o);
    float r = rsqrtf(q * (1.f / 128.f) + 1e-5f);
    float4 gv = ((const float4*)g)[lane];
    float4 bv = ((const float4*)b)[lane];
    float4 o4;
    o4.x = dx * r * gv.x + bv.x;
    o4.y = dy * r * gv.y + bv.y;
    o4.z = dz * r * gv.z + bv.z;
    o4.w = dw * r * gv.w + bv.w;
    ((float4*)(out + (size_t)warp * DIM))[lane] = o4;
}

// ---------------- TF32 tensor-core GEMM core ----------------
// 128x128 block tile, BK=16, 256 threads = 8 warps (2x4), warp tile 64x32.
// MODE 0: C = A@B + bias ; MODE 1: C = res + A@B + bias ; MODE 2: C = gelu(A@B + bias)
#define ASTR 20
#define BSTR 136

template<int MODE, typename OutT>
__device__ __forceinline__ void gemm_body(
    const float* __restrict__ A, const float* __restrict__ B,
    const float* __restrict__ bias, const float* __restrict__ res,
    OutT* __restrict__ C, int M, int K, int Nc, int m0, int n0)
{
    __shared__ float As[2][128 * ASTR];
    __shared__ float Bs[2][16 * BSTR];

    const int tid  = threadIdx.x;
    const int lane = tid & 31;
    const int wid  = tid >> 5;
    const int wr   = wid >> 2;
    const int wc   = wid & 3;

    const int fA0 = tid * 2;

    float acc[4][4][4];
    #pragma unroll
    for (int i = 0; i < 4; i++)
        #pragma unroll
        for (int j = 0; j < 4; j++)
            #pragma unroll
            for (int k = 0; k < 4; k++) acc[i][j][k] = 0.f;

    const int NK = K >> 4;

    auto load_stage = [&](int buf, int kt) {
        #pragma unroll
        for (int i = 0; i < 2; i++) {
            int f   = fA0 + i;
            int row = f >> 2;
            int k4  = (f & 3) * 4;
            bool ok = (m0 + row) < M;
            const float* src = A + (size_t)(ok ? (m0 + row) : 0) * K + kt * 16 + k4;
            uint32_t dst = smem_u32(&As[buf][row * ASTR + k4]);
            CP_ASYNC16(dst, src, ok ? 16 : 0);
        }
        #pragma unroll
        for (int i = 0; i < 2; i++) {
            int f   = fA0 + i;
            int row = f >> 5;
            int n4  = (f & 31) * 4;
            const float* src = B + (size_t)(kt * 16 + row) * Nc + n0 + n4;
            uint32_t dst = smem_u32(&Bs[buf][row * BSTR + n4]);
            CP_ASYNC16(dst, src, 16);
        }
        CP_COMMIT();
    };

    load_stage(0, 0);
    int buf = 0;

    for (int kt = 0; kt < NK; kt++) {
        CP_WAIT0();
        __syncthreads();
        if (kt + 1 < NK) load_stage(buf ^ 1, kt + 1);

        #pragma unroll
        for (int ks = 0; ks < 2; ks++) {
            const int kk = ks * 8;
            uint32_t a[4][4], b[4][2];
            #pragma unroll
            for (int mt = 0; mt < 4; mt++) {
                const float* Ab = &As[buf][(wr * 64 + mt * 16 + (lane >> 2)) * ASTR + kk + (lane & 3)];
                a[mt][0] = __float_as_uint(Ab[0]);
                a[mt][1] = __float_as_uint(Ab[8 * ASTR]);
                a[mt][2] = __float_as_uint(Ab[4]);
                a[mt][3] = __float_as_uint(Ab[8 * ASTR + 4]);
            }
            #pragma unroll
            for (int nt = 0; nt < 4; nt++) {
                const float* Bb = &Bs[buf][(kk + (lane & 3)) * BSTR + wc * 32 + nt * 8 + (lane >> 2)];
                b[nt][0] = __float_as_uint(Bb[0]);
                b[nt][1] = __float_as_uint(Bb[4 * BSTR]);
            }
            #pragma unroll
            for (int mt = 0; mt < 4; mt++)
                #pragma unroll
                for (int nt = 0; nt < 4; nt++) {
                    asm volatile(
                        "mma.sync.aligned.m16n8k8.row.col.f32.tf32.tf32.f32 "
                        "{%0,%1,%2,%3},{%4,%5,%6,%7},{%8,%9},{%0,%1,%2,%3};"
                        : "+f"(acc[mt][nt][0]), "+f"(acc[mt][nt][1]),
                          "+f"(acc[mt][nt][2]), "+f"(acc[mt][nt][3])
                        : "r"(a[mt][0]), "r"(a[mt][1]), "r"(a[mt][2]), "r"(a[mt][3]),
                          "r"(b[nt][0]), "r"(b[nt][1]));
                }
        }
        buf ^= 1;
    }

    #pragma unroll
    for (int mt = 0; mt < 4; mt++) {
        #pragma unroll
        for (int nt = 0; nt < 4; nt++) {
            int r0 = m0 + wr * 64 + mt * 16 + (lane >> 2);
            int c  = n0 + wc * 32 + nt * 8 + (lane & 3) * 2;
            float bx = bias[c], by = bias[c + 1];
            #pragma unroll
            for (int half = 0; half < 2; half++) {
                int r = r0 + half * 8;
                if (r >= M) continue;
                float vx = acc[mt][nt][half * 2 + 0] + bx;
                float vy = acc[mt][nt][half * 2 + 1] + by;
                if (MODE == 1) {
                    const float2 rv = *(const float2*)(res + (size_t)r * Nc + c);
                    vx += rv.x; vy += rv.y;
                }
                if (MODE == 2) {
                    vx = 0.5f * vx * (1.f + erff(vx * 0.70710678118654752f));
                    vy = 0.5f * vy * (1.f + erff(vy * 0.70710678118654752f));
                }
                if (sizeof(OutT) == 2) {
                    *(__half2*)((__half*)C + (size_t)r * Nc + c) = __floats2half2_rn(vx, vy);
                } else {
                    *(float2*)((float*)C + (size_t)r * Nc + c) = make_float2(vx, vy);
                }
            }
        }
    }
}

template<int MODE>
__global__ void __launch_bounds__(256) tgemm_kernel(
    const float* __restrict__ A, const float* __restrict__ B,
    const float* __restrict__ bias, const float* __restrict__ res,
    float* __restrict__ C, int M, int K, int Nc)
{
    gemm_body<MODE, float>(A, B, bias, res, C, M, K, Nc,
                           blockIdx.y * 128, blockIdx.x * 128);
}

// fused Wl/Wr GEMM: blockIdx.x in [0,4): {Wl n0=0, Wl n0=128, Wr n0=0, Wr n0=128}
__global__ void __launch_bounds__(256) tgemm_dual_kernel(
    const float* __restrict__ A,
    const float* __restrict__ Wl, const float* __restrict__ Wr,
    const float* __restrict__ bl, const float* __restrict__ br,
    __half* __restrict__ xl, __half* __restrict__ xr, int M)
{
    const bool right = blockIdx.x >= 2;
    const float* B    = right ? Wr : Wl;
    const float* bias = right ? br : bl;
    __half* C         = right ? xr : xl;
    const int n0 = (blockIdx.x & 1) * 128;
    gemm_body<0, __half>(A, B, bias, nullptr, C, M, DIM, HC,
                         blockIdx.y * 128, n0);
}

// ---------------- effective bias for Wp: bpe = bp + gat_b @ Wp ----------------
__global__ void bpe_kernel(const float* __restrict__ gat_b, const float* __restrict__ Wp,
                           const float* __restrict__ bp, float* __restrict__ out)
{
    int j = threadIdx.x;   // 128
    float s = bp[j];
    #pragma unroll 8
    for (int i = 0; i < HC; i++) s += gat_b[i] * Wp[(size_t)i * DIM + j];
    out[j] = s;
}

// ---------------- edge pass A: scores + segment max (fp16 features) ----------------
// warp per edge; lane i covers channels [8i, 8i+8); lanes 0-15 head0, 16-31 head1
__global__ void edge_score_kernel(const uint4* __restrict__ xl, const uint4* __restrict__ xr,
                                  const int* __restrict__ src, const int* __restrict__ dst,
                                  const float* __restrict__ att,
                                  float* __restrict__ s, float* __restrict__ smax, int ne)
{
    int e    = (blockIdx.x * blockDim.x + threadIdx.x) >> 5;
    int lane = threadIdx.x & 31;
    if (e >= ne) return;
    int sv = src[e], dv = dst[e];

    uint4 lv = xl[(size_t)sv * 32 + lane];
    uint4 rv = xr[(size_t)dv * 32 + lane];
    const float4* a4 = (const float4*)att;
    float4 at0 = a4[lane * 2 + 0];
    float4 at1 = a4[lane * 2 + 1];

    const __half2* lh = (const __half2*)&lv;
    const __half2* rh = (const __half2*)&rv;
    float acc = 0.f;
    float attf[8] = {at0.x, at0.y, at0.z, at0.w, at1.x, at1.y, at1.z, at1.w};
    #pragma unroll
    for (int j = 0; j < 4; j++) {
        float2 lf = __half22float2(lh[j]);
        float2 rf = __half22float2(rh[j]);
        acc += lrelu(lf.x + rf.x) * attf[2 * j]
             + lrelu(lf.y + rf.y) * attf[2 * j + 1];
    }
    // reduce within each 16-lane half (head)
    #pragma unroll
    for (int o = 8; o; o >>= 1) acc += __shfl_xor_sync(~0u, acc, o);
    float s1 = __shfl_sync(~0u, acc, 16);
    if (lane == 0) {
        s[e * 2 + 0] = acc;
        s[e * 2 + 1] = s1;
        atomicMaxF(smax + dv * 2 + 0, acc);
        atomicMaxF(smax + dv * 2 + 1, s1);
    }
}

// ---------------- edge pass B: exp + segment sum ----------------
__global__ void edge_exp_kernel(const float* __restrict__ s, const float* __restrict__ smax,
                                const int* __restrict__ dst,
                                float* __restrict__ ex, float* __restrict__ den, int ne)
{
    int i = blockIdx.x * blockDim.x + threadIdx.x;
    if (i >= 2 * ne) return;
    int e = i >> 1, h = i & 1;
    int d = dst[e];
    float v = expf(s[i] - smax[d * 2 + h]);
    ex[i] = v;
    atomicAdd(den + d * 2 + h, v);
}

// ---------------- edge pass C: weighted aggregate (fp16 gather, fp32 red) ----------------
__global__ void edge_agg_kernel(const uint4* __restrict__ xl,
                                const int* __restrict__ src, const int* __restrict__ dst,
                                const float* __restrict__ ex, const float* __restrict__ den,
                                float* __restrict__ agg, int ne)
{
    int e    = (blockIdx.x * blockDim.x + threadIdx.x) >> 5;
    int lane = threadIdx.x & 31;
    if (e >= ne) return;
    int sv = src[e], dv = dst[e];
    int h  = lane >> 4;
    float a = ex[e * 2 + h] / (den[dv * 2 + h] + 1e-16f);

    uint4 v = xl[(size_t)sv * 32 + lane];
    const __half2* vh = (const __half2*)&v;
    float2 f0 = __half22float2(vh[0]);
    float2 f1 = __half22float2(vh[1]);
    float2 f2 = __half22float2(vh[2]);
    float2 f3 = __half22float2(vh[3]);
    float* p = agg + (size_t)dv * HC + lane * 8;
    red4(p,     f0.x * a, f0.y * a, f1.x * a, f1.y * a);
    red4(p + 4, f2.x * a, f2.y * a, f3.x * a, f3.y * a);
}

// ---------------- host ----------------
extern "C" void kernel_launch(void* const* d_in, const int* in_sizes, int n_in,
                              void* d_out, int out_size)
{
    const float* x     = (const float*)d_in[0];
    const int*   ei    = (const int*)  d_in[1];
    const float* ln1_g = (const float*)d_in[2];
    const float* ln1_b = (const float*)d_in[3];
    const float* Wl    = (const float*)d_in[4];
    const float* bl    = (const float*)d_in[5];
    const float* Wr    = (const float*)d_in[6];
    const float* br    = (const float*)d_in[7];
    const float* att   = (const float*)d_in[8];
    const float* gat_b = (const float*)d_in[9];
    const float* Wp    = (const float*)d_in[10];
    const float* bp    = (const float*)d_in[11];
    const float* ln2_g = (const float*)d_in[12];
    const float* ln2_b = (const float*)d_in[13];
    const float* W1    = (const float*)d_in[14];
    const float* b1    = (const float*)d_in[15];
    const float* W2    = (const float*)d_in[16];
    const float* b2    = (const float*)d_in[17];

    const int n  = NN;
    const int ne = EE;
    const int* src = ei;
    const int* dst = ei + ne;

    float *gx, *gh, *gagg, *gmlp, *gs, *gex, *gsmax, *gden, *gbpe;
    __half *gxlh, *gxrh;
    cudaGetSymbolAddress((void**)&gx,   g_x);
    cudaGetSymbolAddress((void**)&gh,   g_h);
    cudaGetSymbolAddress((void**)&gxlh, g_xlh);
    cudaGetSymbolAddress((void**)&gxrh, g_xrh);
    cudaGetSymbolAddress((void**)&gagg, g_agg);
    cudaGetSymbolAddress((void**)&gmlp, g_mlp);
    cudaGetSymbolAddress((void**)&gs,   g_s);
    cudaGetSymbolAddress((void**)&gex,  g_ex);
    cudaGetSymbolAddress((void**)&gsmax,g_smax);
    cudaGetSymbolAddress((void**)&gden, g_den);
    cudaGetSymbolAddress((void**)&gbpe, g_bpe);

    cudaMemcpyAsync(gx, x, sizeof(float) * (size_t)n * DIM, cudaMemcpyDeviceToDevice);

    const int lnBlocks   = (n + 7) / 8;
    const int edgeBlocks = (ne + 7) / 8;
    const int mBlocks    = (n + 127) / 128;   // 391

    for (int l = 0; l < 2; l++) {
        // --- attention block ---
        ln_kernel<<<lnBlocks, 256>>>(gx, ln1_g + l * DIM, ln1_b + l * DIM, gh, n);

        tgemm_dual_kernel<<<dim3(4, mBlocks), 256>>>(
            gh, Wl + (size_t)l * DIM * HC, Wr + (size_t)l * DIM * HC,
            bl + l * HC, br + l * HC, gxlh, gxrh, n);

        cudaMemsetAsync(gagg, 0, sizeof(float) * (size_t)n * HC);
        cudaMemsetAsync(gden, 0, sizeof(float) * (size_t)n * 2);
        cudaMemsetAsync(gsmax, 0xFF, sizeof(float) * (size_t)n * 2);  // -NaN bits: identity for atomicMaxF

        edge_score_kernel<<<edgeBlocks, 256>>>((const uint4*)gxlh, (const uint4*)gxrh,
                                               src, dst, att + l * HC, gs, gsmax, ne);
        edge_exp_kernel<<<(2 * ne + 255) / 256, 256>>>(gs, gsmax, dst, gex, gden, ne);
        edge_agg_kernel<<<edgeBlocks, 256>>>((const uint4*)gxlh, src, dst, gex, gden, gagg, ne);

        bpe_kernel<<<1, DIM>>>(gat_b + l * HC, Wp + (size_t)l * HC * DIM, bp + l * DIM, gbpe);
        tgemm_kernel<1><<<dim3(DIM / 128, mBlocks), 256>>>(
            gagg, Wp + (size_t)l * HC * DIM, gbpe, gx, gx, n, HC, DIM);

        // --- MLP block ---
        ln_kernel<<<lnBlocks, 256>>>(gx, ln2_g + l * DIM, ln2_b + l * DIM, gh, n);

        tgemm_kernel<2><<<dim3(DMLP / 128, mBlocks), 256>>>(
            gh, W1 + (size_t)l * DIM * DMLP, b1 + l * DMLP, nullptr, gmlp, n, DIM, DMLP);

        tgemm_kernel<1><<<dim3(DIM / 128, mBlocks), 256>>>(
            gmlp, W2 + (size_t)l * DMLP * DIM, b2 + l * DIM, gx, gx, n, DMLP, DIM);
    }

    cudaMemcpyAsync(d_out, gx, sizeof(float) * (size_t)n * DIM, cudaMemcpyDeviceToDevice);
}

// round 6
// speedup vs baseline: 1.4779x; 1.4779x over previous
#include <cuda_runtime.h>
#include <cuda_fp16.h>
#include <math.h>
#include <stdint.h>

#define NN 50000
#define EE 800000
#define DIM 128
#define HC 256        // HEADS*DIM
#define DMLP 512

// ---------------- scratch (device globals; no allocation) ----------------
__device__ float  g_x     [NN * DIM];
__device__ float  g_h     [NN * DIM];
__device__ __half g_xlh   [NN * HC];
__device__ __half g_xrh   [NN * HC];
__device__ float  g_agg   [NN * HC];
__device__ float  g_mlp   [NN * DMLP];
__device__ float  g_bpe   [DIM];
__device__ int    g_deg   [NN];
__device__ int    g_rowptr[NN + 1];
__device__ int    g_fill  [NN];
__device__ int    g_ssrc  [EE];

// ---------------- helpers ----------------
__device__ __forceinline__ float lrelu(float v) { return v > 0.f ? v : 0.2f * v; }

__device__ __forceinline__ uint32_t smem_u32(const void* p) {
    return (uint32_t)__cvta_generic_to_shared(p);
}

#define CP_ASYNC16(dst, src, szbytes) \
    asm volatile("cp.async.cg.shared.global [%0], [%1], 16, %2;" \
                 :: "r"(dst), "l"(src), "r"(szbytes))
#define CP_COMMIT()  asm volatile("cp.async.commit_group;")
#define CP_WAIT0()   asm volatile("cp.async.wait_group 0;")

// ---------------- CSR build ----------------
__global__ void hist_kernel(const int* __restrict__ dst, int* __restrict__ deg, int ne)
{
    int e = blockIdx.x * blockDim.x + threadIdx.x;
    if (e < ne) atomicAdd(&deg[dst[e]], 1);
}

__global__ void scan_kernel(const int* __restrict__ deg, int* __restrict__ rowptr, int n)
{
    __shared__ int sm[1024];
    __shared__ int carry_s;
    int tid = threadIdx.x;
    if (tid == 0) carry_s = 0;
    __syncthreads();
    for (int base = 0; base < n; base += 1024) {
        int i = base + tid;
        int v = (i < n) ? deg[i] : 0;
        sm[tid] = v;
        __syncthreads();
        #pragma unroll
        for (int off = 1; off < 1024; off <<= 1) {
            int t = (tid >= off) ? sm[tid - off] : 0;
            __syncthreads();
            sm[tid] += t;
            __syncthreads();
        }
        int incl = sm[tid];
        int carry = carry_s;
        if (i < n) rowptr[i] = carry + incl - v;   // exclusive
        __syncthreads();
        if (tid == 1023) carry_s = carry + sm[1023];
        __syncthreads();
    }
    if (tid == 0) rowptr[n] = carry_s;
}

__global__ void scatter_kernel(const int* __restrict__ src, const int* __restrict__ dst,
                               const int* __restrict__ rowptr, int* __restrict__ fill,
                               int* __restrict__ ssrc, int ne)
{
    int e = blockIdx.x * blockDim.x + threadIdx.x;
    if (e >= ne) return;
    int d = dst[e];
    int pos = rowptr[d] + atomicAdd(&fill[d], 1);
    ssrc[pos] = src[e];
}

// ---------------- layernorm: warp per row ----------------
__global__ void ln_kernel(const float* __restrict__ x, const float* __restrict__ g,
                          const float* __restrict__ b, float* __restrict__ out, int n)
{
    int warp = (blockIdx.x * blockDim.x + threadIdx.x) >> 5;
    int lane = threadIdx.x & 31;
    if (warp >= n) return;
    const float4 v = ((const float4*)(x + (size_t)warp * DIM))[lane];
    float s = v.x + v.y + v.z + v.w;
    #pragma unroll
    for (int o = 16; o; o >>= 1) s += __shfl_xor_sync(~0u, s, o);
    float mu = s * (1.f / 128.f);
    float dx = v.x - mu, dy = v.y - mu, dz = v.z - mu, dw = v.w - mu;
    float q = dx*dx + dy*dy + dz*dz + dw*dw;
    #pragma unroll
    for (int o = 16; o; o >>= 1) q += __shfl_xor_sync(~0u, q, o);
    float r = rsqrtf(q * (1.f / 128.f) + 1e-5f);
    float4 gv = ((const float4*)g)[lane];
    float4 bv = ((const float4*)b)[lane];
    float4 o4;
    o4.x = dx * r * gv.x + bv.x;
    o4.y = dy * r * gv.y + bv.y;
    o4.z = dz * r * gv.z + bv.z;
    o4.w = dw * r * gv.w + bv.w;
    ((float4*)(out + (size_t)warp * DIM))[lane] = o4;
}

// ---------------- TF32 tensor-core GEMM core ----------------
#define ASTR 20
#define BSTR 136

template<int MODE, typename OutT>
__device__ __forceinline__ void gemm_body(
    const float* __restrict__ A, const float* __restrict__ B,
    const float* __restrict__ bias, const float* __restrict__ res,
    OutT* __restrict__ C, int M, int K, int Nc, int m0, int n0)
{
    __shared__ float As[2][128 * ASTR];
    __shared__ float Bs[2][16 * BSTR];

    const int tid  = threadIdx.x;
    const int lane = tid & 31;
    const int wid  = tid >> 5;
    const int wr   = wid >> 2;
    const int wc   = wid & 3;
    const int fA0  = tid * 2;

    float acc[4][4][4];
    #pragma unroll
    for (int i = 0; i < 4; i++)
        #pragma unroll
        for (int j = 0; j < 4; j++)
            #pragma unroll
            for (int k = 0; k < 4; k++) acc[i][j][k] = 0.f;

    const int NK = K >> 4;

    auto load_stage = [&](int buf, int kt) {
        #pragma unroll
        for (int i = 0; i < 2; i++) {
            int f   = fA0 + i;
            int row = f >> 2;
            int k4  = (f & 3) * 4;
            bool ok = (m0 + row) < M;
            const float* src = A + (size_t)(ok ? (m0 + row) : 0) * K + kt * 16 + k4;
            uint32_t dstp = smem_u32(&As[buf][row * ASTR + k4]);
            CP_ASYNC16(dstp, src, ok ? 16 : 0);
        }
        #pragma unroll
        for (int i = 0; i < 2; i++) {
            int f   = fA0 + i;
            int row = f >> 5;
            int n4  = (f & 31) * 4;
            const float* src = B + (size_t)(kt * 16 + row) * Nc + n0 + n4;
            uint32_t dstp = smem_u32(&Bs[buf][row * BSTR + n4]);
            CP_ASYNC16(dstp, src, 16);
        }
        CP_COMMIT();
    };

    load_stage(0, 0);
    int buf = 0;

    for (int kt = 0; kt < NK; kt++) {
        CP_WAIT0();
        __syncthreads();
        if (kt + 1 < NK) load_stage(buf ^ 1, kt + 1);

        #pragma unroll
        for (int ks = 0; ks < 2; ks++) {
            const int kk = ks * 8;
            uint32_t a[4][4], b[4][2];
            #pragma unroll
            for (int mt = 0; mt < 4; mt++) {
                const float* Ab = &As[buf][(wr * 64 + mt * 16 + (lane >> 2)) * ASTR + kk + (lane & 3)];
                a[mt][0] = __float_as_uint(Ab[0]);
                a[mt][1] = __float_as_uint(Ab[8 * ASTR]);
                a[mt][2] = __float_as_uint(Ab[4]);
                a[mt][3] = __float_as_uint(Ab[8 * ASTR + 4]);
            }
            #pragma unroll
            for (int nt = 0; nt < 4; nt++) {
                const float* Bb = &Bs[buf][(kk + (lane & 3)) * BSTR + wc * 32 + nt * 8 + (lane >> 2)];
                b[nt][0] = __float_as_uint(Bb[0]);
                b[nt][1] = __float_as_uint(Bb[4 * BSTR]);
            }
            #pragma unroll
            for (int mt = 0; mt < 4; mt++)
                #pragma unroll
                for (int nt = 0; nt < 4; nt++) {
                    asm volatile(
                        "mma.sync.aligned.m16n8k8.row.col.f32.tf32.tf32.f32 "
                        "{%0,%1,%2,%3},{%4,%5,%6,%7},{%8,%9},{%0,%1,%2,%3};"
                        : "+f"(acc[mt][nt][0]), "+f"(acc[mt][nt][1]),
                          "+f"(acc[mt][nt][2]), "+f"(acc[mt][nt][3])
                        : "r"(a[mt][0]), "r"(a[mt][1]), "r"(a[mt][2]), "r"(a[mt][3]),
                          "r"(b[nt][0]), "r"(b[nt][1]));
                }
        }
        buf ^= 1;
    }

    #pragma unroll
    for (int mt = 0; mt < 4; mt++) {
        #pragma unroll
        for (int nt = 0; nt < 4; nt++) {
            int r0 = m0 + wr * 64 + mt * 16 + (lane >> 2);
            int c  = n0 + wc * 32 + nt * 8 + (lane & 3) * 2;
            float bx = bias[c], by = bias[c + 1];
            #pragma unroll
            for (int half = 0; half < 2; half++) {
                int r = r0 + half * 8;
                if (r >= M) continue;
                float vx = acc[mt][nt][half * 2 + 0] + bx;
                float vy = acc[mt][nt][half * 2 + 1] + by;
                if (MODE == 1) {
                    const float2 rv = *(const float2*)(res + (size_t)r * Nc + c);
                    vx += rv.x; vy += rv.y;
                }
                if (MODE == 2) {
                    vx = 0.5f * vx * (1.f + erff(vx * 0.70710678118654752f));
                    vy = 0.5f * vy * (1.f + erff(vy * 0.70710678118654752f));
                }
                if (sizeof(OutT) == 2) {
                    *(__half2*)((__half*)C + (size_t)r * Nc + c) = __floats2half2_rn(vx, vy);
                } else {
                    *(float2*)((float*)C + (size_t)r * Nc + c) = make_float2(vx, vy);
                }
            }
        }
    }
}

template<int MODE>
__global__ void __launch_bounds__(256) tgemm_kernel(
    const float* __restrict__ A, const float* __restrict__ B,
    const float* __restrict__ bias, const float* __restrict__ res,
    float* __restrict__ C, int M, int K, int Nc)
{
    gemm_body<MODE, float>(A, B, bias, res, C, M, K, Nc,
                           blockIdx.y * 128, blockIdx.x * 128);
}

__global__ void __launch_bounds__(256) tgemm_half_kernel(
    const float* __restrict__ A, const float* __restrict__ B,
    const float* __restrict__ bias,
    __half* __restrict__ C, int M, int K, int Nc)
{
    gemm_body<0, __half>(A, B, bias, nullptr, C, M, K, Nc,
                         blockIdx.y * 128, blockIdx.x * 128);
}

// ---------------- effective bias for Wp: bpe = bp + gat_b @ Wp ----------------
__global__ void bpe_kernel(const float* __restrict__ gat_b, const float* __restrict__ Wp,
                           const float* __restrict__ bp, float* __restrict__ out)
{
    int j = threadIdx.x;   // 128
    float s = bp[j];
    #pragma unroll 8
    for (int i = 0; i < HC; i++) s += gat_b[i] * Wp[(size_t)i * DIM + j];
    out[j] = s;
}

// ---------------- fused GATv2 edge phase: warp per dst, online softmax ----------------
// lane i owns channels [8i, 8i+8); lanes 0-15 = head0, lanes 16-31 = head1.
__global__ void __launch_bounds__(256) gat_fused_kernel(
    const uint4* __restrict__ xl, const uint4* __restrict__ xr,
    const int* __restrict__ rowptr, const int* __restrict__ ssrc,
    const float* __restrict__ att, float* __restrict__ agg, int n)
{
    int d    = (blockIdx.x * blockDim.x + threadIdx.x) >> 5;
    int lane = threadIdx.x & 31;
    if (d >= n) return;

    int beg = rowptr[d];
    int end = rowptr[d + 1];

    // unpack xr[d] and att for my 8 channels
    float rf[8], attv[8];
    {
        uint4 rv = xr[(size_t)d * 32 + lane];
        const __half2* rh = (const __half2*)&rv;
        #pragma unroll
        for (int j = 0; j < 4; j++) {
            float2 f = __half22float2(rh[j]);
            rf[2 * j] = f.x; rf[2 * j + 1] = f.y;
        }
        float4 a0 = ((const float4*)att)[lane * 2 + 0];
        float4 a1 = ((const float4*)att)[lane * 2 + 1];
        attv[0] = a0.x; attv[1] = a0.y; attv[2] = a0.z; attv[3] = a0.w;
        attv[4] = a1.x; attv[5] = a1.y; attv[6] = a1.z; attv[7] = a1.w;
    }

    float m   = -3.402823466e38f;   // per-head running max
    float den = 0.f;
    float acc[8];
    #pragma unroll
    for (int j = 0; j < 8; j++) acc[j] = 0.f;

    // 1-deep prefetch pipeline over incoming edges
    uint4 lv;
    if (beg < end) lv = xl[(size_t)ssrc[beg] * 32 + lane];

    for (int e = beg; e < end; e++) {
        uint4 cur = lv;
        if (e + 1 < end) lv = xl[(size_t)ssrc[e + 1] * 32 + lane];

        float lf[8];
        const __half2* lh = (const __half2*)&cur;
        #pragma unroll
        for (int j = 0; j < 4; j++) {
            float2 f = __half22float2(lh[j]);
            lf[2 * j] = f.x; lf[2 * j + 1] = f.y;
        }
        float partial = 0.f;
        #pragma unroll
        for (int j = 0; j < 8; j++)
            partial += lrelu(lf[j] + rf[j]) * attv[j];
        // reduce within each 16-lane half (per head)
        #pragma unroll
        for (int o = 8; o; o >>= 1) partial += __shfl_xor_sync(~0u, partial, o);
        float s = partial;

        float mnew  = fmaxf(m, s);
        float scale = __expf(m - mnew);   // exp(-inf)=0 on first edge
        float ex    = __expf(s - mnew);
        den = den * scale + ex;
        #pragma unroll
        for (int j = 0; j < 8; j++) acc[j] = acc[j] * scale + ex * lf[j];
        m = mnew;
    }

    float inv = 1.f / (den + 1e-16f);
    float4 o0 = make_float4(acc[0] * inv, acc[1] * inv, acc[2] * inv, acc[3] * inv);
    float4 o1 = make_float4(acc[4] * inv, acc[5] * inv, acc[6] * inv, acc[7] * inv);
    float* p = agg + (size_t)d * HC + lane * 8;
    *(float4*)p       = o0;
    *(float4*)(p + 4) = o1;
}

// ---------------- host ----------------
extern "C" void kernel_launch(void* const* d_in, const int* in_sizes, int n_in,
                              void* d_out, int out_size)
{
    const float* x     = (const float*)d_in[0];
    const int*   ei    = (const int*)  d_in[1];
    const float* ln1_g = (const float*)d_in[2];
    const float* ln1_b = (const float*)d_in[3];
    const float* Wl    = (const float*)d_in[4];
    const float* bl    = (const float*)d_in[5];
    const float* Wr    = (const float*)d_in[6];
    const float* br    = (const float*)d_in[7];
    const float* att   = (const float*)d_in[8];
    const float* gat_b = (const float*)d_in[9];
    const float* Wp    = (const float*)d_in[10];
    const float* bp    = (const float*)d_in[11];
    const float* ln2_g = (const float*)d_in[12];
    const float* ln2_b = (const float*)d_in[13];
    const float* W1    = (const float*)d_in[14];
    const float* b1    = (const float*)d_in[15];
    const float* W2    = (const float*)d_in[16];
    const float* b2    = (const float*)d_in[17];

    const int n  = NN;
    const int ne = EE;
    const int* src = ei;
    const int* dst = ei + ne;

    float *gx, *gh, *gagg, *gmlp, *gbpe;
    __half *gxlh, *gxrh;
    int *gdeg, *growptr, *gfill, *gssrc;
    cudaGetSymbolAddress((void**)&gx,     g_x);
    cudaGetSymbolAddress((void**)&gh,     g_h);
    cudaGetSymbolAddress((void**)&gxlh,   g_xlh);
    cudaGetSymbolAddress((void**)&gxrh,   g_xrh);
    cudaGetSymbolAddress((void**)&gagg,   g_agg);
    cudaGetSymbolAddress((void**)&gmlp,   g_mlp);
    cudaGetSymbolAddress((void**)&gbpe,   g_bpe);
    cudaGetSymbolAddress((void**)&gdeg,   g_deg);
    cudaGetSymbolAddress((void**)&growptr,g_rowptr);
    cudaGetSymbolAddress((void**)&gfill,  g_fill);
    cudaGetSymbolAddress((void**)&gssrc,  g_ssrc);

    cudaMemcpyAsync(gx, x, sizeof(float) * (size_t)n * DIM, cudaMemcpyDeviceToDevice);

    // ---- CSR build (amortized over both layers) ----
    cudaMemsetAsync(gdeg,  0, sizeof(int) * n);
    cudaMemsetAsync(gfill, 0, sizeof(int) * n);
    hist_kernel<<<(ne + 255) / 256, 256>>>(dst, gdeg, ne);
    scan_kernel<<<1, 1024>>>(gdeg, growptr, n);
    scatter_kernel<<<(ne + 255) / 256, 256>>>(src, dst, growptr, gfill, gssrc, ne);

    const int lnBlocks  = (n + 7) / 8;
    const int gatBlocks = (n + 7) / 8;
    const int mBlocks   = (n + 127) / 128;   // 391

    for (int l = 0; l < 2; l++) {
        // --- attention block ---
        ln_kernel<<<lnBlocks, 256>>>(gx, ln1_g + l * DIM, ln1_b + l * DIM, gh, n);

        tgemm_half_kernel<<<dim3(HC / 128, mBlocks), 256>>>(
            gh, Wl + (size_t)l * DIM * HC, bl + l * HC, gxlh, n, DIM, HC);
        tgemm_half_kernel<<<dim3(HC / 128, mBlocks), 256>>>(
            gh, Wr + (size_t)l * DIM * HC, br + l * HC, gxrh, n, DIM, HC);

        gat_fused_kernel<<<gatBlocks, 256>>>((const uint4*)gxlh, (const uint4*)gxrh,
                                             growptr, gssrc, att + l * HC, gagg, n);

        bpe_kernel<<<1, DIM>>>(gat_b + l * HC, Wp + (size_t)l * HC * DIM, bp + l * DIM, gbpe);
        tgemm_kernel<1><<<dim3(DIM / 128, mBlocks), 256>>>(
            gagg, Wp + (size_t)l * HC * DIM, gbpe, gx, gx, n, HC, DIM);

        // --- MLP block ---
        ln_kernel<<<lnBlocks, 256>>>(gx, ln2_g + l * DIM, ln2_b + l * DIM, gh, n);

        tgemm_kernel<2><<<dim3(DMLP / 128, mBlocks), 256>>>(
            gh, W1 + (size_t)l * DIM * DMLP, b1 + l * DMLP, nullptr, gmlp, n, DIM, DMLP);

        tgemm_kernel<1><<<dim3(DIM / 128, mBlocks), 256>>>(
            gmlp, W2 + (size_t)l * DMLP * DIM, b2 + l * DIM, gx, gx, n, DMLP, DIM);
    }

    cudaMemcpyAsync(d_out, gx, sizeof(float) * (size_t)n * DIM, cudaMemcpyDeviceToDevice);
}

// round 8
// speedup vs baseline: 1.8696x; 1.2650x over previous
#include <cuda_runtime.h>
#include <cuda_fp16.h>
#include <math.h>
#include <stdint.h>

#define NN 50000
#define EE 800000
#define DIM 128
#define HC 256        // HEADS*DIM
#define DMLP 512
#define DEPTH 2

// ---------------- scratch (device globals; no allocation) ----------------
__device__ float  g_x     [NN * DIM];     // residual stream (fp32)
__device__ __half g_hh    [NN * DIM];     // layernorm output (fp16)
__device__ __half g_xlh   [NN * HC];
__device__ __half g_xrh   [NN * HC];
__device__ __half g_aggh  [NN * HC];
__device__ __half g_mlph  [NN * DMLP];
__device__ float  g_bpe   [DIM];
__device__ int    g_deg   [NN];
__device__ int    g_rowptr[NN + 1];
__device__ int    g_fill  [NN];
__device__ int    g_ssrc  [EE];
// fp16 weights
__device__ __half g_Wlh [DEPTH * DIM * HC];
__device__ __half g_Wrh [DEPTH * DIM * HC];
__device__ __half g_Wph [DEPTH * HC * DIM];
__device__ __half g_W1h [DEPTH * DIM * DMLP];
__device__ __half g_W2h [DEPTH * DMLP * DIM];

// ---------------- helpers ----------------
__device__ __forceinline__ float lrelu(float v) { return v > 0.f ? v : 0.2f * v; }

__device__ __forceinline__ uint32_t smem_u32(const void* p) {
    return (uint32_t)__cvta_generic_to_shared(p);
}

#define CP_ASYNC16(dst, src, szbytes) \
    asm volatile("cp.async.cg.shared.global [%0], [%1], 16, %2;" \
                 :: "r"(dst), "l"(src), "r"(szbytes))
#define CP_COMMIT()  asm volatile("cp.async.commit_group;")
#define CP_WAIT0()   asm volatile("cp.async.wait_group 0;")

#define LDSM4(r0, r1, r2, r3, addr) \
    asm volatile("ldmatrix.sync.aligned.m8n8.x4.shared.b16 {%0,%1,%2,%3},[%4];" \
                 : "=r"(r0), "=r"(r1), "=r"(r2), "=r"(r3) : "r"(addr))
#define LDSM4T(r0, r1, r2, r3, addr) \
    asm volatile("ldmatrix.sync.aligned.m8n8.x4.trans.shared.b16 {%0,%1,%2,%3},[%4];" \
                 : "=r"(r0), "=r"(r1), "=r"(r2), "=r"(r3) : "r"(addr))

// ---------------- fp32 -> fp16 conversion ----------------
__global__ void f2h_kernel(const float* __restrict__ s, __half* __restrict__ d, int n)
{
    int i = blockIdx.x * blockDim.x + threadIdx.x;
    int stride = gridDim.x * blockDim.x;
    for (; i < n; i += stride) d[i] = __float2half_rn(s[i]);
}

// ---------------- CSR build ----------------
__global__ void hist_kernel(const int* __restrict__ dst, int* __restrict__ deg, int ne)
{
    int e = blockIdx.x * blockDim.x + threadIdx.x;
    if (e < ne) atomicAdd(&deg[dst[e]], 1);
}

__global__ void scan_kernel(const int* __restrict__ deg, int* __restrict__ rowptr, int n)
{
    __shared__ int sm[1024];
    __shared__ int carry_s;
    int tid = threadIdx.x;
    if (tid == 0) carry_s = 0;
    __syncthreads();
    for (int base = 0; base < n; base += 1024) {
        int i = base + tid;
        int v = (i < n) ? deg[i] : 0;
        sm[tid] = v;
        __syncthreads();
        #pragma unroll
        for (int off = 1; off < 1024; off <<= 1) {
            int t = (tid >= off) ? sm[tid - off] : 0;
            __syncthreads();
            sm[tid] += t;
            __syncthreads();
        }
        int incl = sm[tid];
        int carry = carry_s;
        if (i < n) rowptr[i] = carry + incl - v;   // exclusive
        __syncthreads();
        if (tid == 1023) carry_s = carry + sm[1023];
        __syncthreads();
    }
    if (tid == 0) rowptr[n] = carry_s;
}

__global__ void scatter_kernel(const int* __restrict__ src, const int* __restrict__ dst,
                               const int* __restrict__ rowptr, int* __restrict__ fill,
                               int* __restrict__ ssrc, int ne)
{
    int e = blockIdx.x * blockDim.x + threadIdx.x;
    if (e >= ne) return;
    int d = dst[e];
    int pos = rowptr[d] + atomicAdd(&fill[d], 1);
    ssrc[pos] = src[e];
}

// ---------------- layernorm: warp per row, fp16 out ----------------
__global__ void ln_kernel(const float* __restrict__ x, const float* __restrict__ g,
                          const float* __restrict__ b, __half* __restrict__ out, int n)
{
    int warp = (blockIdx.x * blockDim.x + threadIdx.x) >> 5;
    int lane = threadIdx.x & 31;
    if (warp >= n) return;
    const float4 v = ((const float4*)(x + (size_t)warp * DIM))[lane];
    float s = v.x + v.y + v.z + v.w;
    #pragma unroll
    for (int o = 16; o; o >>= 1) s += __shfl_xor_sync(~0u, s, o);
    float mu = s * (1.f / 128.f);
    float dx = v.x - mu, dy = v.y - mu, dz = v.z - mu, dw = v.w - mu;
    float q = dx*dx + dy*dy + dz*dz + dw*dw;
    #pragma unroll
    for (int o = 16; o; o >>= 1) q += __shfl_xor_sync(~0u, q, o);
    float r = rsqrtf(q * (1.f / 128.f) + 1e-5f);
    float4 gv = ((const float4*)g)[lane];
    float4 bv = ((const float4*)b)[lane];
    __half2 h0 = __floats2half2_rn(dx * r * gv.x + bv.x, dy * r * gv.y + bv.y);
    __half2 h1 = __floats2half2_rn(dz * r * gv.z + bv.z, dw * r * gv.w + bv.w);
    __half2* op = (__half2*)(out + (size_t)warp * DIM);
    op[lane * 2 + 0] = h0;
    op[lane * 2 + 1] = h1;
}

// ---------------- fp16 tensor-core GEMM core ----------------
// 128x128 block tile, BK=32, 256 threads = 8 warps (2x4), warp tile 64x32, mma m16n8k16.
// MODE 0: C = A@B + bias ; MODE 1: C = res + A@B + bias ; MODE 2: C = gelu(A@B + bias)
#define SA 40     // A smem row stride (halfs)
#define SB 136    // B smem row stride (halfs)

template<int MODE, typename OutT>
__device__ __forceinline__ void hgemm_body(
    const __half* __restrict__ A, const __half* __restrict__ B,
    const float* __restrict__ bias, const float* __restrict__ res,
    OutT* __restrict__ C, int M, int K, int Nc, int m0, int n0)
{
    __shared__ __half As[2][128 * SA];
    __shared__ __half Bs[2][32 * SB];

    const int tid  = threadIdx.x;
    const int lane = tid & 31;
    const int wid  = tid >> 5;
    const int wr   = wid >> 2;          // warp row (64 rows)
    const int wc   = wid & 3;           // warp col (32 cols)

    float acc[4][4][4];
    #pragma unroll
    for (int i = 0; i < 4; i++)
        #pragma unroll
        for (int j = 0; j < 4; j++)
            #pragma unroll
            for (int k = 0; k < 4; k++) acc[i][j][k] = 0.f;

    const int NK = K >> 5;

    auto load_stage = [&](int buf, int kt) {
        // A: 128 rows x 32 halfs = 512 x 16B chunks
        #pragma unroll
        for (int i = 0; i < 2; i++) {
            int f   = tid * 2 + i;
            int row = f >> 2;
            int ch  = (f & 3) * 8;
            bool ok = (m0 + row) < M;
            const __half* src = A + (size_t)(ok ? (m0 + row) : 0) * K + kt * 32 + ch;
            CP_ASYNC16(smem_u32(&As[buf][row * SA + ch]), src, ok ? 16 : 0);
        }
        // B: 32 rows x 128 halfs = 512 x 16B chunks
        #pragma unroll
        for (int i = 0; i < 2; i++) {
            int f   = tid * 2 + i;
            int row = f >> 4;
            int ch  = (f & 15) * 8;
            const __half* src = B + (size_t)(kt * 32 + row) * Nc + n0 + ch;
            CP_ASYNC16(smem_u32(&Bs[buf][row * SB + ch]), src, 16);
        }
        CP_COMMIT();
    };

    load_stage(0, 0);
    int buf = 0;

    for (int kt = 0; kt < NK; kt++) {
        CP_WAIT0();
        __syncthreads();
        if (kt + 1 < NK) load_stage(buf ^ 1, kt + 1);

        #pragma unroll
        for (int ks = 0; ks < 2; ks++) {
            const int kk = ks * 16;
            uint32_t a[4][4], b[4][2];
            #pragma unroll
            for (int mt = 0; mt < 4; mt++) {
                uint32_t addr = smem_u32(
                    &As[buf][(wr * 64 + mt * 16 + (lane & 15)) * SA + kk + (lane >> 4) * 8]);
                LDSM4(a[mt][0], a[mt][1], a[mt][2], a[mt][3], addr);
            }
            #pragma unroll
            for (int nh = 0; nh < 2; nh++) {
                uint32_t addr = smem_u32(
                    &Bs[buf][(kk + (lane & 15)) * SB + wc * 32 + nh * 16 + (lane >> 4) * 8]);
                LDSM4T(b[nh * 2][0], b[nh * 2][1], b[nh * 2 + 1][0], b[nh * 2 + 1][1], addr);
            }
            #pragma unroll
            for (int mt = 0; mt < 4; mt++)
                #pragma unroll
                for (int nt = 0; nt < 4; nt++) {
                    asm volatile(
                        "mma.sync.aligned.m16n8k16.row.col.f32.f16.f16.f32 "
                        "{%0,%1,%2,%3},{%4,%5,%6,%7},{%8,%9},{%0,%1,%2,%3};"
                        : "+f"(acc[mt][nt][0]), "+f"(acc[mt][nt][1]),
                          "+f"(acc[mt][nt][2]), "+f"(acc[mt][nt][3])
                        : "r"(a[mt][0]), "r"(a[mt][1]), "r"(a[mt][2]), "r"(a[mt][3]),
                          "r"(b[nt][0]), "r"(b[nt][1]));
                }
        }
        buf ^= 1;
    }

    // epilogue (m16n8 accumulator layout)
    #pragma unroll
    for (int mt = 0; mt < 4; mt++) {
        #pragma unroll
        for (int nt = 0; nt < 4; nt++) {
            int r0 = m0 + wr * 64 + mt * 16 + (lane >> 2);
            int c  = n0 + wc * 32 + nt * 8 + (lane & 3) * 2;
            float bx = bias[c], by = bias[c + 1];
            #pragma unroll
            for (int half = 0; half < 2; half++) {
                int r = r0 + half * 8;
                if (r >= M) continue;
                float vx = acc[mt][nt][half * 2 + 0] + bx;
                float vy = acc[mt][nt][half * 2 + 1] + by;
                if (MODE == 1) {
                    const float2 rv = *(const float2*)(res + (size_t)r * Nc + c);
                    vx += rv.x; vy += rv.y;
                }
                if (MODE == 2) {
                    vx = 0.5f * vx * (1.f + erff(vx * 0.70710678118654752f));
                    vy = 0.5f * vy * (1.f + erff(vy * 0.70710678118654752f));
                }
                if (sizeof(OutT) == 2) {
                    *(__half2*)((__half*)C + (size_t)r * Nc + c) = __floats2half2_rn(vx, vy);
                } else {
                    *(float2*)((float*)C + (size_t)r * Nc + c) = make_float2(vx, vy);
                }
            }
        }
    }
}

template<int MODE>
__global__ void __launch_bounds__(256) hgemm_f32_kernel(
    const __half* __restrict__ A, const __half* __restrict__ B,
    const float* __restrict__ bias, const float* __restrict__ res,
    float* __restrict__ C, int M, int K, int Nc)
{
    hgemm_body<MODE, float>(A, B, bias, res, C, M, K, Nc,
                            blockIdx.y * 128, blockIdx.x * 128);
}

template<int MODE>
__global__ void __launch_bounds__(256) hgemm_f16_kernel(
    const __half* __restrict__ A, const __half* __restrict__ B,
    const float* __restrict__ bias,
    __half* __restrict__ C, int M, int K, int Nc)
{
    hgemm_body<MODE, __half>(A, B, bias, nullptr, C, M, K, Nc,
                             blockIdx.y * 128, blockIdx.x * 128);
}

// ---------------- effective bias for Wp: bpe = bp + gat_b @ Wp (fp32 weights) ----------------
__global__ void bpe_kernel(const float* __restrict__ gat_b, const float* __restrict__ Wp,
                           const float* __restrict__ bp, float* __restrict__ out)
{
    int j = threadIdx.x;   // 128
    float s = bp[j];
    #pragma unroll 8
    for (int i = 0; i < HC; i++) s += gat_b[i] * Wp[(size_t)i * DIM + j];
    out[j] = s;
}

// ---------------- fused GATv2 edge phase: warp per dst, online softmax ----------------
__global__ void __launch_bounds__(256) gat_fused_kernel(
    const uint4* __restrict__ xl, const uint4* __restrict__ xr,
    const int* __restrict__ rowptr, const int* __restrict__ ssrc,
    const float* __restrict__ att, __half* __restrict__ agg, int n)
{
    int d    = (blockIdx.x * blockDim.x + threadIdx.x) >> 5;
    int lane = threadIdx.x & 31;
    if (d >= n) return;

    int beg = rowptr[d];
    int end = rowptr[d + 1];

    float rf[8], attv[8];
    {
        uint4 rv = xr[(size_t)d * 32 + lane];
        const __half2* rh = (const __half2*)&rv;
        #pragma unroll
        for (int j = 0; j < 4; j++) {
            float2 f = __half22float2(rh[j]);
            rf[2 * j] = f.x; rf[2 * j + 1] = f.y;
        }
        float4 a0 = ((const float4*)att)[lane * 2 + 0];
        float4 a1 = ((const float4*)att)[lane * 2 + 1];
        attv[0] = a0.x; attv[1] = a0.y; attv[2] = a0.z; attv[3] = a0.w;
        attv[4] = a1.x; attv[5] = a1.y; attv[6] = a1.z; attv[7] = a1.w;
    }

    float m   = -3.402823466e38f;
    float den = 0.f;
    float acc[8];
    #pragma unroll
    for (int j = 0; j < 8; j++) acc[j] = 0.f;

    uint4 lv;
    if (beg < end) lv = xl[(size_t)ssrc[beg] * 32 + lane];

    for (int e = beg; e < end; e++) {
        uint4 cur = lv;
        if (e + 1 < end) lv = xl[(size_t)ssrc[e + 1] * 32 + lane];

        float lf[8];
        const __half2* lh = (const __half2*)&cur;
        #pragma unroll
        for (int j = 0; j < 4; j++) {
            float2 f = __half22float2(lh[j]);
            lf[2 * j] = f.x; lf[2 * j + 1] = f.y;
        }
        float partial = 0.f;
        #pragma unroll
        for (int j = 0; j < 8; j++)
            partial += lrelu(lf[j] + rf[j]) * attv[j];
        #pragma unroll
        for (int o = 8; o; o >>= 1) partial += __shfl_xor_sync(~0u, partial, o);
        float s = partial;

        float mnew  = fmaxf(m, s);
        float scale = __expf(m - mnew);
        float ex    = __expf(s - mnew);
        den = den * scale + ex;
        #pragma unroll
        for (int j = 0; j < 8; j++) acc[j] = acc[j] * scale + ex * lf[j];
        m = mnew;
    }

    float inv = 1.f / (den + 1e-16f);
    uint4 outp;
    __half2* oh = (__half2*)&outp;
    oh[0] = __floats2half2_rn(acc[0] * inv, acc[1] * inv);
    oh[1] = __floats2half2_rn(acc[2] * inv, acc[3] * inv);
    oh[2] = __floats2half2_rn(acc[4] * inv, acc[5] * inv);
    oh[3] = __floats2half2_rn(acc[6] * inv, acc[7] * inv);
    *(uint4*)(agg + (size_t)d * HC + lane * 8) = outp;
}

// ---------------- host ----------------
extern "C" void kernel_launch(void* const* d_in, const int* in_sizes, int n_in,
                              void* d_out, int out_size)
{
    const float* x     = (const float*)d_in[0];
    const int*   ei    = (const int*)  d_in[1];
    const float* ln1_g = (const float*)d_in[2];
    const float* ln1_b = (const float*)d_in[3];
    const float* Wl    = (const float*)d_in[4];
    const float* bl    = (const float*)d_in[5];
    const float* Wr    = (const float*)d_in[6];
    const float* br    = (const float*)d_in[7];
    const float* att   = (const float*)d_in[8];
    const float* gat_b = (const float*)d_in[9];
    const float* Wp    = (const float*)d_in[10];
    const float* bp    = (const float*)d_in[11];
    const float* ln2_g = (const float*)d_in[12];
    const float* ln2_b = (const float*)d_in[13];
    const float* W1    = (const float*)d_in[14];
    const float* b1    = (const float*)d_in[15];
    const float* W2    = (const float*)d_in[16];
    const float* b2    = (const float*)d_in[17];

    const int n  = NN;
    const int ne = EE;
    const int* src = ei;
    const int* dst = ei + ne;

    float *gx, *gbpe;
    __half *ghh, *gxlh, *gxrh, *gaggh, *gmlph;
    __half *gWlh, *gWrh, *gWph, *gW1h, *gW2h;
    int *gdeg, *growptr, *gfill, *gssrc;
    cudaGetSymbolAddress((void**)&gx,     g_x);
    cudaGetSymbolAddress((void**)&ghh,    g_hh);
    cudaGetSymbolAddress((void**)&gxlh,   g_xlh);
    cudaGetSymbolAddress((void**)&gxrh,   g_xrh);
    cudaGetSymbolAddress((void**)&gaggh,  g_aggh);
    cudaGetSymbolAddress((void**)&gmlph,  g_mlph);
    cudaGetSymbolAddress((void**)&gbpe,   g_bpe);
    cudaGetSymbolAddress((void**)&gdeg,   g_deg);
    cudaGetSymbolAddress((void**)&growptr,g_rowptr);
    cudaGetSymbolAddress((void**)&gfill,  g_fill);
    cudaGetSymbolAddress((void**)&gssrc,  g_ssrc);
    cudaGetSymbolAddress((void**)&gWlh,   g_Wlh);
    cudaGetSymbolAddress((void**)&gWrh,   g_Wrh);
    cudaGetSymbolAddress((void**)&gWph,   g_Wph);
    cudaGetSymbolAddress((void**)&gW1h,   g_W1h);
    cudaGetSymbolAddress((void**)&gW2h,   g_W2h);

    cudaMemcpyAsync(gx, x, sizeof(float) * (size_t)n * DIM, cudaMemcpyDeviceToDevice);

    // ---- weight conversion (fp32 -> fp16) ----
    f2h_kernel<<<256, 256>>>(Wl, gWlh, DEPTH * DIM * HC);
    f2h_kernel<<<256, 256>>>(Wr, gWrh, DEPTH * DIM * HC);
    f2h_kernel<<<256, 256>>>(Wp, gWph, DEPTH * HC * DIM);
    f2h_kernel<<<256, 256>>>(W1, gW1h, DEPTH * DIM * DMLP);
    f2h_kernel<<<256, 256>>>(W2, gW2h, DEPTH * DMLP * DIM);

    // ---- CSR build (amortized over both layers) ----
    cudaMemsetAsync(gdeg,  0, sizeof(int) * n);
    cudaMemsetAsync(gfill, 0, sizeof(int) * n);
    hist_kernel<<<(ne + 255) / 256, 256>>>(dst, gdeg, ne);
    scan_kernel<<<1, 1024>>>(gdeg, growptr, n);
    scatter_kernel<<<(ne + 255) / 256, 256>>>(src, dst, growptr, gfill, gssrc, ne);

    const int lnBlocks  = (n + 7) / 8;
    const int gatBlocks = (n + 7) / 8;
    const int mBlocks   = (n + 127) / 128;   // 391

    for (int l = 0; l < 2; l++) {
        // --- attention block ---
        ln_kernel<<<lnBlocks, 256>>>(gx, ln1_g + l * DIM, ln1_b + l * DIM, ghh, n);

        hgemm_f16_kernel<0><<<dim3(HC / 128, mBlocks), 256>>>(
            ghh, gWlh + (size_t)l * DIM * HC, bl + l * HC, gxlh, n, DIM, HC);
        hgemm_f16_kernel<0><<<dim3(HC / 128, mBlocks), 256>>>(
            ghh, gWrh + (size_t)l * DIM * HC, br + l * HC, gxrh, n, DIM, HC);

        gat_fused_kernel<<<gatBlocks, 256>>>((const uint4*)gxlh, (const uint4*)gxrh,
                                             growptr, gssrc, att + l * HC, gaggh, n);

        bpe_kernel<<<1, DIM>>>(gat_b + l * HC, Wp + (size_t)l * HC * DIM, bp + l * DIM, gbpe);
        hgemm_f32_kernel<1><<<dim3(DIM / 128, mBlocks), 256>>>(
            gaggh, gWph + (size_t)l * HC * DIM, gbpe, gx, gx, n, HC, DIM);

        // --- MLP block ---
        ln_kernel<<<lnBlocks, 256>>>(gx, ln2_g + l * DIM, ln2_b + l * DIM, ghh, n);

        hgemm_f16_kernel<2><<<dim3(DMLP / 128, mBlocks), 256>>>(
            ghh, gW1h + (size_t)l * DIM * DMLP, b1 + l * DMLP, gmlph, n, DIM, DMLP);

        hgemm_f32_kernel<1><<<dim3(DIM / 128, mBlocks), 256>>>(
            gmlph, gW2h + (size_t)l * DMLP * DIM, b2 + l * DIM, gx, gx, n, DMLP, DIM);
    }

    cudaMemcpyAsync(d_out, gx, sizeof(float) * (size_t)n * DIM, cudaMemcpyDeviceToDevice);
}

// round 9
// speedup vs baseline: 2.0582x; 1.1009x over previous
#include <cuda_runtime.h>
#include <cuda_fp16.h>
#include <math.h>
#include <stdint.h>

#define NN 50000
#define EE 800000
#define DIM 128
#define HC 256        // HEADS*DIM
#define DMLP 512
#define DEPTH 2

// ---------------- scratch (device globals; no allocation) ----------------
__device__ float  g_x     [NN * DIM];     // residual stream (fp32)
__device__ __half g_hh    [NN * DIM];     // layernorm output (fp16)
__device__ __half g_xlh   [NN * HC];
__device__ __half g_xrh   [NN * HC];
__device__ __half g_aggh  [NN * HC];
__device__ __half g_mlph  [NN * DMLP];
__device__ float  g_bpe   [DEPTH * DIM];
__device__ int    g_deg   [NN];
__device__ int    g_rowptr[NN + 1];
__device__ int    g_fill  [NN];
__device__ int    g_ssrc  [EE];
// fp16 weights
__device__ __half g_Wlh [DEPTH * DIM * HC];
__device__ __half g_Wrh [DEPTH * DIM * HC];
__device__ __half g_Wph [DEPTH * HC * DIM];
__device__ __half g_W1h [DEPTH * DIM * DMLP];
__device__ __half g_W2h [DEPTH * DMLP * DIM];

// ---------------- helpers ----------------
__device__ __forceinline__ float lrelu(float v) { return v > 0.f ? v : 0.2f * v; }

__device__ __forceinline__ uint32_t smem_u32(const void* p) {
    return (uint32_t)__cvta_generic_to_shared(p);
}

#define CP_ASYNC16(dst, src, szbytes) \
    asm volatile("cp.async.cg.shared.global [%0], [%1], 16, %2;" \
                 :: "r"(dst), "l"(src), "r"(szbytes))
#define CP_COMMIT()  asm volatile("cp.async.commit_group;")
#define CP_WAIT0()   asm volatile("cp.async.wait_group 0;")

#define LDSM4(r0, r1, r2, r3, addr) \
    asm volatile("ldmatrix.sync.aligned.m8n8.x4.shared.b16 {%0,%1,%2,%3},[%4];" \
                 : "=r"(r0), "=r"(r1), "=r"(r2), "=r"(r3) : "r"(addr))
#define LDSM4T(r0, r1, r2, r3, addr) \
    asm volatile("ldmatrix.sync.aligned.m8n8.x4.trans.shared.b16 {%0,%1,%2,%3},[%4];" \
                 : "=r"(r0), "=r"(r1), "=r"(r2), "=r"(r3) : "r"(addr))

// ---------------- fp32 -> fp16 conversion (all weights, one launch) ----------------
#define NW1 (DEPTH * DIM * HC)      // Wl
#define NW3 (DEPTH * HC * DIM)      // Wp
#define NW4 (DEPTH * DIM * DMLP)    // W1
#define NW5 (DEPTH * DMLP * DIM)    // W2
#define NWTOT (NW1 + NW1 + NW3 + NW4 + NW5)

__global__ void f2h_all_kernel(const float* __restrict__ Wl, const float* __restrict__ Wr,
                               const float* __restrict__ Wp, const float* __restrict__ W1,
                               const float* __restrict__ W2,
                               __half* __restrict__ oWl, __half* __restrict__ oWr,
                               __half* __restrict__ oWp, __half* __restrict__ oW1,
                               __half* __restrict__ oW2)
{
    int i = blockIdx.x * blockDim.x + threadIdx.x;
    int stride = gridDim.x * blockDim.x;
    for (; i < NWTOT; i += stride) {
        int j = i;
        if (j < NW1)               { oWl[j] = __float2half_rn(Wl[j]); continue; }
        j -= NW1;
        if (j < NW1)               { oWr[j] = __float2half_rn(Wr[j]); continue; }
        j -= NW1;
        if (j < NW3)               { oWp[j] = __float2half_rn(Wp[j]); continue; }
        j -= NW3;
        if (j < NW4)               { oW1[j] = __float2half_rn(W1[j]); continue; }
        j -= NW4;
        oW2[j] = __float2half_rn(W2[j]);
    }
}

// ---------------- CSR build ----------------
__global__ void hist_kernel(const int* __restrict__ dst, int* __restrict__ deg, int ne)
{
    int e = blockIdx.x * blockDim.x + threadIdx.x;
    if (e < ne) atomicAdd(&deg[dst[e]], 1);
}

__global__ void scan_kernel(const int* __restrict__ deg, int* __restrict__ rowptr, int n)
{
    __shared__ int sm[1024];
    __shared__ int carry_s;
    int tid = threadIdx.x;
    if (tid == 0) carry_s = 0;
    __syncthreads();
    for (int base = 0; base < n; base += 1024) {
        int i = base + tid;
        int v = (i < n) ? deg[i] : 0;
        sm[tid] = v;
        __syncthreads();
        #pragma unroll
        for (int off = 1; off < 1024; off <<= 1) {
            int t = (tid >= off) ? sm[tid - off] : 0;
            __syncthreads();
            sm[tid] += t;
            __syncthreads();
        }
        int incl = sm[tid];
        int carry = carry_s;
        if (i < n) rowptr[i] = carry + incl - v;   // exclusive
        __syncthreads();
        if (tid == 1023) carry_s = carry + sm[1023];
        __syncthreads();
    }
    if (tid == 0) rowptr[n] = carry_s;
}

__global__ void scatter_kernel(const int* __restrict__ src, const int* __restrict__ dst,
                               const int* __restrict__ rowptr, int* __restrict__ fill,
                               int* __restrict__ ssrc, int ne)
{
    int e = blockIdx.x * blockDim.x + threadIdx.x;
    if (e >= ne) return;
    int d = dst[e];
    int pos = rowptr[d] + atomicAdd(&fill[d], 1);
    ssrc[pos] = src[e];
}

// ---------------- standalone layernorm (layer-0 LN1 only): warp per row ----------------
__global__ void ln_kernel(const float* __restrict__ x, const float* __restrict__ g,
                          const float* __restrict__ b, __half* __restrict__ out, int n)
{
    int warp = (blockIdx.x * blockDim.x + threadIdx.x) >> 5;
    int lane = threadIdx.x & 31;
    if (warp >= n) return;
    const float4 v = ((const float4*)(x + (size_t)warp * DIM))[lane];
    float s = v.x + v.y + v.z + v.w;
    #pragma unroll
    for (int o = 16; o; o >>= 1) s += __shfl_xor_sync(~0u, s, o);
    float mu = s * (1.f / 128.f);
    float dx = v.x - mu, dy = v.y - mu, dz = v.z - mu, dw = v.w - mu;
    float q = dx*dx + dy*dy + dz*dz + dw*dw;
    #pragma unroll
    for (int o = 16; o; o >>= 1) q += __shfl_xor_sync(~0u, q, o);
    float r = rsqrtf(q * (1.f / 128.f) + 1e-5f);
    float4 gv = ((const float4*)g)[lane];
    float4 bv = ((const float4*)b)[lane];
    __half2 h0 = __floats2half2_rn(dx * r * gv.x + bv.x, dy * r * gv.y + bv.y);
    __half2 h1 = __floats2half2_rn(dz * r * gv.z + bv.z, dw * r * gv.w + bv.w);
    __half2* op = (__half2*)(out + (size_t)warp * DIM);
    op[lane * 2 + 0] = h0;
    op[lane * 2 + 1] = h1;
}

// ---------------- fp16 tensor-core GEMM mainloop ----------------
// 128x128 block tile, BK=32, 256 threads = 8 warps (2x4), warp tile 64x32, mma m16n8k16.
#define SA 40     // A smem row stride (halfs)
#define SB 136    // B smem row stride (halfs)
#define AS_HALFS (128 * SA)      // per buffer
#define BS_HALFS (32 * SB)
#define SMEM_PLAIN_BYTES (2 * AS_HALFS * 2 + 2 * BS_HALFS * 2)   // 37888
#define TSTR 132
#define SMEM_LN_BYTES (128 * TSTR * 4)                            // 67584

__device__ __forceinline__ void hgemm_mainloop(
    const __half* __restrict__ A, const __half* __restrict__ B,
    int M, int K, int Nc, int m0, int n0,
    __half* As, __half* Bs, float (&acc)[4][4][4])
{
    const int tid  = threadIdx.x;
    const int lane = tid & 31;
    const int wid  = tid >> 5;
    const int wr   = wid >> 2;
    const int wc   = wid & 3;

    #pragma unroll
    for (int i = 0; i < 4; i++)
        #pragma unroll
        for (int j = 0; j < 4; j++)
            #pragma unroll
            for (int k = 0; k < 4; k++) acc[i][j][k] = 0.f;

    const int NK = K >> 5;

    auto load_stage = [&](int buf, int kt) {
        __half* Ab = As + buf * AS_HALFS;
        __half* Bb = Bs + buf * BS_HALFS;
        #pragma unroll
        for (int i = 0; i < 2; i++) {
            int f   = tid * 2 + i;
            int row = f >> 2;
            int ch  = (f & 3) * 8;
            bool ok = (m0 + row) < M;
            const __half* src = A + (size_t)(ok ? (m0 + row) : 0) * K + kt * 32 + ch;
            CP_ASYNC16(smem_u32(&Ab[row * SA + ch]), src, ok ? 16 : 0);
        }
        #pragma unroll
        for (int i = 0; i < 2; i++) {
            int f   = tid * 2 + i;
            int row = f >> 4;
            int ch  = (f & 15) * 8;
            const __half* src = B + (size_t)(kt * 32 + row) * Nc + n0 + ch;
            CP_ASYNC16(smem_u32(&Bb[row * SB + ch]), src, 16);
        }
        CP_COMMIT();
    };

    load_stage(0, 0);
    int buf = 0;

    for (int kt = 0; kt < NK; kt++) {
        CP_WAIT0();
        __syncthreads();
        if (kt + 1 < NK) load_stage(buf ^ 1, kt + 1);
        __half* Ab = As + buf * AS_HALFS;
        __half* Bb = Bs + buf * BS_HALFS;

        #pragma unroll
        for (int ks = 0; ks < 2; ks++) {
            const int kk = ks * 16;
            uint32_t a[4][4], b[4][2];
            #pragma unroll
            for (int mt = 0; mt < 4; mt++) {
                uint32_t addr = smem_u32(
                    &Ab[(wr * 64 + mt * 16 + (lane & 15)) * SA + kk + (lane >> 4) * 8]);
                LDSM4(a[mt][0], a[mt][1], a[mt][2], a[mt][3], addr);
            }
            #pragma unroll
            for (int nh = 0; nh < 2; nh++) {
                uint32_t addr = smem_u32(
                    &Bb[(kk + (lane & 15)) * SB + wc * 32 + nh * 16 + (lane >> 4) * 8]);
                LDSM4T(b[nh * 2][0], b[nh * 2][1], b[nh * 2 + 1][0], b[nh * 2 + 1][1], addr);
            }
            #pragma unroll
            for (int mt = 0; mt < 4; mt++)
                #pragma unroll
                for (int nt = 0; nt < 4; nt++) {
                    asm volatile(
                        "mma.sync.aligned.m16n8k16.row.col.f32.f16.f16.f32 "
                        "{%0,%1,%2,%3},{%4,%5,%6,%7},{%8,%9},{%0,%1,%2,%3};"
                        : "+f"(acc[mt][nt][0]), "+f"(acc[mt][nt][1]),
                          "+f"(acc[mt][nt][2]), "+f"(acc[mt][nt][3])
                        : "r"(a[mt][0]), "r"(a[mt][1]), "r"(a[mt][2]), "r"(a[mt][3]),
                          "r"(b[nt][0]), "r"(b[nt][1]));
                }
        }
        buf ^= 1;
    }
}

// ---------------- plain GEMM kernels ----------------
// MODE 0: C = A@B + bias ; MODE 1: C = res + A@B + bias ; MODE 2: C = gelu(A@B + bias)
template<int MODE, typename OutT>
__device__ __forceinline__ void hgemm_epilogue(
    float (&acc)[4][4][4], const float* __restrict__ bias, const float* __restrict__ res,
    OutT* __restrict__ C, int M, int Nc, int m0, int n0)
{
    const int lane = threadIdx.x & 31;
    const int wid  = threadIdx.x >> 5;
    const int wr   = wid >> 2;
    const int wc   = wid & 3;
    #pragma unroll
    for (int mt = 0; mt < 4; mt++) {
        #pragma unroll
        for (int nt = 0; nt < 4; nt++) {
            int r0 = m0 + wr * 64 + mt * 16 + (lane >> 2);
            int c  = n0 + wc * 32 + nt * 8 + (lane & 3) * 2;
            float bx = bias[c], by = bias[c + 1];
            #pragma unroll
            for (int half = 0; half < 2; half++) {
                int r = r0 + half * 8;
                if (r >= M) continue;
                float vx = acc[mt][nt][half * 2 + 0] + bx;
                float vy = acc[mt][nt][half * 2 + 1] + by;
                if (MODE == 1) {
                    const float2 rv = *(const float2*)(res + (size_t)r * Nc + c);
                    vx += rv.x; vy += rv.y;
                }
                if (MODE == 2) {
                    vx = 0.5f * vx * (1.f + erff(vx * 0.70710678118654752f));
                    vy = 0.5f * vy * (1.f + erff(vy * 0.70710678118654752f));
                }
                if (sizeof(OutT) == 2) {
                    *(__half2*)((__half*)C + (size_t)r * Nc + c) = __floats2half2_rn(vx, vy);
                } else {
                    *(float2*)((float*)C + (size_t)r * Nc + c) = make_float2(vx, vy);
                }
            }
        }
    }
}

template<int MODE>
__global__ void __launch_bounds__(256) hgemm_f32_kernel(
    const __half* __restrict__ A, const __half* __restrict__ B,
    const float* __restrict__ bias, const float* __restrict__ res,
    float* __restrict__ C, int M, int K, int Nc)
{
    __shared__ __align__(16) char smraw[SMEM_PLAIN_BYTES];
    __half* As = (__half*)smraw;
    __half* Bs = (__half*)(smraw + 2 * AS_HALFS * 2);
    float acc[4][4][4];
    hgemm_mainloop(A, B, M, K, Nc, blockIdx.y * 128, blockIdx.x * 128, As, Bs, acc);
    hgemm_epilogue<MODE, float>(acc, bias, res, C, M, Nc, blockIdx.y * 128, blockIdx.x * 128);
}

template<int MODE>
__global__ void __launch_bounds__(256) hgemm_f16_kernel(
    const __half* __restrict__ A, const __half* __restrict__ B,
    const float* __restrict__ bias,
    __half* __restrict__ C, int M, int K, int Nc)
{
    __shared__ __align__(16) char smraw[SMEM_PLAIN_BYTES];
    __half* As = (__half*)smraw;
    __half* Bs = (__half*)(smraw + 2 * AS_HALFS * 2);
    float acc[4][4][4];
    hgemm_mainloop(A, B, M, K, Nc, blockIdx.y * 128, blockIdx.x * 128, As, Bs, acc);
    hgemm_epilogue<MODE, __half>(acc, bias, nullptr, C, M, Nc, blockIdx.y * 128, blockIdx.x * 128);
}

// ---------------- GEMM (Nc=128) + residual + fused LayerNorm ----------------
// C_raw = res + A@B + bias  -> xout (fp32), hout = LN(C_raw) (fp16)
// Uses dynamic smem: union of (As,Bs) and fp32 tile T[128][TSTR].
__global__ void __launch_bounds__(256) hgemm_ln_kernel(
    const __half* __restrict__ A, const __half* __restrict__ B,
    const float* __restrict__ bias, const float* __restrict__ res,
    float* __restrict__ xout, const float* __restrict__ ln_g,
    const float* __restrict__ ln_b, __half* __restrict__ hout,
    int M, int K)
{
    extern __shared__ __align__(16) char smraw[];
    __half* As = (__half*)smraw;
    __half* Bs = (__half*)(smraw + 2 * AS_HALFS * 2);
    float*  T  = (float*)smraw;

    const int m0   = blockIdx.y * 128;
    const int lane = threadIdx.x & 31;
    const int wid  = threadIdx.x >> 5;
    const int wr   = wid >> 2;
    const int wc   = wid & 3;

    float acc[4][4][4];
    hgemm_mainloop(A, B, M, K, DIM, m0, 0, As, Bs, acc);
    __syncthreads();   // all warps done with As/Bs before T overwrites them

    // write raw fp32 tile to smem
    #pragma unroll
    for (int mt = 0; mt < 4; mt++) {
        #pragma unroll
        for (int nt = 0; nt < 4; nt++) {
            int rr0 = wr * 64 + mt * 16 + (lane >> 2);
            int c   = wc * 32 + nt * 8 + (lane & 3) * 2;
            float bx = bias[c], by = bias[c + 1];
            #pragma unroll
            for (int half = 0; half < 2; half++) {
                int rr = rr0 + half * 8;
                int r  = m0 + rr;
                float vx = acc[mt][nt][half * 2 + 0] + bx;
                float vy = acc[mt][nt][half * 2 + 1] + by;
                if (r < M) {
                    const float2 rv = *(const float2*)(res + (size_t)r * DIM + c);
                    vx += rv.x; vy += rv.y;
                }
                T[rr * TSTR + c]     = vx;
                T[rr * TSTR + c + 1] = vy;
            }
        }
    }
    __syncthreads();

    // LN: warp wid handles rows [wid*16, wid*16+16)
    float4 gv = ((const float4*)ln_g)[lane];
    float4 bv = ((const float4*)ln_b)[lane];
    for (int rr = wid * 16; rr < wid * 16 + 16; rr++) {
        int r = m0 + rr;
        if (r >= M) break;
        float4 v;
        v.x = T[rr * TSTR + lane * 4 + 0];
        v.y = T[rr * TSTR + lane * 4 + 1];
        v.z = T[rr * TSTR + lane * 4 + 2];
        v.w = T[rr * TSTR + lane * 4 + 3];
        float s = v.x + v.y + v.z + v.w;
        #pragma unroll
        for (int o = 16; o; o >>= 1) s += __shfl_xor_sync(~0u, s, o);
        float mu = s * (1.f / 128.f);
        float dx = v.x - mu, dy = v.y - mu, dz = v.z - mu, dw = v.w - mu;
        float q = dx*dx + dy*dy + dz*dz + dw*dw;
        #pragma unroll
        for (int o = 16; o; o >>= 1) q += __shfl_xor_sync(~0u, q, o);
        float rs = rsqrtf(q * (1.f / 128.f) + 1e-5f);
        // write raw x
        ((float4*)(xout + (size_t)r * DIM))[lane] = v;
        // write normalized fp16 h
        __half2 h0 = __floats2half2_rn(dx * rs * gv.x + bv.x, dy * rs * gv.y + bv.y);
        __half2 h1 = __floats2half2_rn(dz * rs * gv.z + bv.z, dw * rs * gv.w + bv.w);
        __half2* op = (__half2*)(hout + (size_t)r * DIM);
        op[lane * 2 + 0] = h0;
        op[lane * 2 + 1] = h1;
    }
}

// ---------------- effective bias for Wp (both layers): bpe = bp + gat_b @ Wp ----------------
__global__ void bpe_kernel(const float* __restrict__ gat_b, const float* __restrict__ Wp,
                           const float* __restrict__ bp, float* __restrict__ out)
{
    int l = blockIdx.x;    // layer
    int j = threadIdx.x;   // 128
    const float* W = Wp + (size_t)l * HC * DIM;
    const float* gb = gat_b + l * HC;
    float s = bp[l * DIM + j];
    #pragma unroll 8
    for (int i = 0; i < HC; i++) s += gb[i] * W[(size_t)i * DIM + j];
    out[l * DIM + j] = s;
}

// ---------------- fused GATv2 edge phase: warp per dst, online softmax, depth-2 prefetch ----------------
__global__ void __launch_bounds__(256) gat_fused_kernel(
    const uint4* __restrict__ xl, const uint4* __restrict__ xr,
    const int* __restrict__ rowptr, const int* __restrict__ ssrc,
    const float* __restrict__ att, __half* __restrict__ agg, int n)
{
    int d    = (blockIdx.x * blockDim.x + threadIdx.x) >> 5;
    int lane = threadIdx.x & 31;
    if (d >= n) return;

    int beg = rowptr[d];
    int end = rowptr[d + 1];

    float rf[8], attv[8];
    {
        uint4 rv = xr[(size_t)d * 32 + lane];
        const __half2* rh = (const __half2*)&rv;
        #pragma unroll
        for (int j = 0; j < 4; j++) {
            float2 f = __half22float2(rh[j]);
            rf[2 * j] = f.x; rf[2 * j + 1] = f.y;
        }
        float4 a0 = ((const float4*)att)[lane * 2 + 0];
        float4 a1 = ((const float4*)att)[lane * 2 + 1];
        attv[0] = a0.x; attv[1] = a0.y; attv[2] = a0.z; attv[3] = a0.w;
        attv[4] = a1.x; attv[5] = a1.y; attv[6] = a1.z; attv[7] = a1.w;
    }

    float m   = -3.402823466e38f;
    float den = 0.f;
    float acc[8];
    #pragma unroll
    for (int j = 0; j < 8; j++) acc[j] = 0.f;

    // depth-2 prefetch pipeline
    uint4 pf0, pf1;
    if (beg < end)     pf0 = xl[(size_t)ssrc[beg] * 32 + lane];
    if (beg + 1 < end) pf1 = xl[(size_t)ssrc[beg + 1] * 32 + lane];

    for (int e = beg; e < end; e++) {
        uint4 cur = pf0;
        pf0 = pf1;
        if (e + 2 < end) pf1 = xl[(size_t)ssrc[e + 2] * 32 + lane];

        float lf[8];
        const __half2* lh = (const __half2*)&cur;
        #pragma unroll
        for (int j = 0; j < 4; j++) {
            float2 f = __half22float2(lh[j]);
            lf[2 * j] = f.x; lf[2 * j + 1] = f.y;
        }
        float partial = 0.f;
        #pragma unroll
        for (int j = 0; j < 8; j++)
            partial += lrelu(lf[j] + rf[j]) * attv[j];
        #pragma unroll
        for (int o = 8; o; o >>= 1) partial += __shfl_xor_sync(~0u, partial, o);
        float s = partial;

        float mnew  = fmaxf(m, s);
        float scale = __expf(m - mnew);
        float ex    = __expf(s - mnew);
        den = den * scale + ex;
        #pragma unroll
        for (int j = 0; j < 8; j++) acc[j] = acc[j] * scale + ex * lf[j];
        m = mnew;
    }

    float inv = 1.f / (den + 1e-16f);
    uint4 outp;
    __half2* oh = (__half2*)&outp;
    oh[0] = __floats2half2_rn(acc[0] * inv, acc[1] * inv);
    oh[1] = __floats2half2_rn(acc[2] * inv, acc[3] * inv);
    oh[2] = __floats2half2_rn(acc[4] * inv, acc[5] * inv);
    oh[3] = __floats2half2_rn(acc[6] * inv, acc[7] * inv);
    *(uint4*)(agg + (size_t)d * HC + lane * 8) = outp;
}

// ---------------- host ----------------
extern "C" void kernel_launch(void* const* d_in, const int* in_sizes, int n_in,
                              void* d_out, int out_size)
{
    const float* x     = (const float*)d_in[0];
    const int*   ei    = (const int*)  d_in[1];
    const float* ln1_g = (const float*)d_in[2];
    const float* ln1_b = (const float*)d_in[3];
    const float* Wl    = (const float*)d_in[4];
    const float* bl    = (const float*)d_in[5];
    const float* Wr    = (const float*)d_in[6];
    const float* br    = (const float*)d_in[7];
    const float* att   = (const float*)d_in[8];
    const float* gat_b = (const float*)d_in[9];
    const float* Wp    = (const float*)d_in[10];
    const float* bp    = (const float*)d_in[11];
    const float* ln2_g = (const float*)d_in[12];
    const float* ln2_b = (const float*)d_in[13];
    const float* W1    = (const float*)d_in[14];
    const float* b1    = (const float*)d_in[15];
    const float* W2    = (const float*)d_in[16];
    const float* b2    = (const float*)d_in[17];

    const int n  = NN;
    const int ne = EE;
    const int* src = ei;
    const int* dst = ei + ne;

    float *gx, *gbpe;
    __half *ghh, *gxlh, *gxrh, *gaggh, *gmlph;
    __half *gWlh, *gWrh, *gWph, *gW1h, *gW2h;
    int *gdeg, *growptr, *gfill, *gssrc;
    cudaGetSymbolAddress((void**)&gx,     g_x);
    cudaGetSymbolAddress((void**)&ghh,    g_hh);
    cudaGetSymbolAddress((void**)&gxlh,   g_xlh);
    cudaGetSymbolAddress((void**)&gxrh,   g_xrh);
    cudaGetSymbolAddress((void**)&gaggh,  g_aggh);
    cudaGetSymbolAddress((void**)&gmlph,  g_mlph);
    cudaGetSymbolAddress((void**)&gbpe,   g_bpe);
    cudaGetSymbolAddress((void**)&gdeg,   g_deg);
    cudaGetSymbolAddress((void**)&growptr,g_rowptr);
    cudaGetSymbolAddress((void**)&gfill,  g_fill);
    cudaGetSymbolAddress((void**)&gssrc,  g_ssrc);
    cudaGetSymbolAddress((void**)&gWlh,   g_Wlh);
    cudaGetSymbolAddress((void**)&gWrh,   g_Wrh);
    cudaGetSymbolAddress((void**)&gWph,   g_Wph);
    cudaGetSymbolAddress((void**)&gW1h,   g_W1h);
    cudaGetSymbolAddress((void**)&gW2h,   g_W2h);

    cudaFuncSetAttribute(hgemm_ln_kernel,
                         cudaFuncAttributeMaxDynamicSharedMemorySize, SMEM_LN_BYTES);

    // ---- preludes (no inter-dependence with layer loop state) ----
    f2h_all_kernel<<<448, 256>>>(Wl, Wr, Wp, W1, W2, gWlh, gWrh, gWph, gW1h, gW2h);
    bpe_kernel<<<2, DIM>>>(gat_b, Wp, bp, gbpe);

    cudaMemsetAsync(gdeg,  0, sizeof(int) * n);
    cudaMemsetAsync(gfill, 0, sizeof(int) * n);
    hist_kernel<<<(ne + 255) / 256, 256>>>(dst, gdeg, ne);
    scan_kernel<<<1, 1024>>>(gdeg, growptr, n);
    scatter_kernel<<<(ne + 255) / 256, 256>>>(src, dst, growptr, gfill, gssrc, ne);

    // layer-0 LN1 directly from input
    ln_kernel<<<(n + 7) / 8, 256>>>(x, ln1_g, ln1_b, ghh, n);

    const int gatBlocks = (n + 7) / 8;
    const int mBlocks   = (n + 127) / 128;   // 391

    for (int l = 0; l < 2; l++) {
        const float* resx = (l == 0) ? x : gx;   // residual input to Wp GEMM

        hgemm_f16_kernel<0><<<dim3(HC / 128, mBlocks), 256>>>(
            ghh, gWlh + (size_t)l * DIM * HC, bl + l * HC, gxlh, n, DIM, HC);
        hgemm_f16_kernel<0><<<dim3(HC / 128, mBlocks), 256>>>(
            ghh, gWrh + (size_t)l * DIM * HC, br + l * HC, gxrh, n, DIM, HC);

        gat_fused_kernel<<<gatBlocks, 256>>>((const uint4*)gxlh, (const uint4*)gxrh,
                                             growptr, gssrc, att + l * HC, gaggh, n);

        // x = resx + agg@Wp + bpe ; h = LN2(x)
        hgemm_ln_kernel<<<dim3(1, mBlocks), 256, SMEM_LN_BYTES>>>(
            gaggh, gWph + (size_t)l * HC * DIM, gbpe + l * DIM, resx,
            gx, ln2_g + l * DIM, ln2_b + l * DIM, ghh, n, HC);

        hgemm_f16_kernel<2><<<dim3(DMLP / 128, mBlocks), 256>>>(
            ghh, gW1h + (size_t)l * DIM * DMLP, b1 + l * DMLP, gmlph, n, DIM, DMLP);

        if (l == 0) {
            // x = x + mlp@W2 + b2 ; h = LN1_layer1(x)
            hgemm_ln_kernel<<<dim3(1, mBlocks), 256, SMEM_LN_BYTES>>>(
                gmlph, gW2h, b2, gx,
                gx, ln1_g + DIM, ln1_b + DIM, ghh, n, DMLP);
        } else {
            // final: write d_out directly
            hgemm_f32_kernel<1><<<dim3(1, mBlocks), 256>>>(
                gmlph, gW2h + (size_t)DMLP * DIM, b2 + DIM, gx,
                (float*)d_out, n, DMLP, DIM);
        }
    }
}

// round 10
// speedup vs baseline: 2.2807x; 1.1081x over previous
#include <cuda_runtime.h>
#include <cuda_fp16.h>
#include <math.h>
#include <stdint.h>

#define NN 50000
#define EE 800000
#define DIM 128
#define HC 256        // HEADS*DIM
#define DMLP 512
#define DEPTH 2

#define SCAN_CHUNK 1024
#define SCAN_NB ((NN + SCAN_CHUNK - 1) / SCAN_CHUNK)   // 49

// ---------------- scratch (device globals; no allocation) ----------------
__device__ float  g_x     [NN * DIM];     // residual stream (fp32)
__device__ __half g_hh    [NN * DIM];     // layernorm output (fp16)
__device__ __half g_xlh   [NN * HC];
__device__ __half g_xrh   [NN * HC];
__device__ __half g_aggh  [NN * HC];
__device__ __half g_mlph  [NN * DMLP];
__device__ float  g_bpe   [DEPTH * DIM];
__device__ int    g_deg   [NN];
__device__ int    g_rowptr[NN + 1];
__device__ int    g_fill  [NN];
__device__ int    g_ssrc  [EE];
__device__ int    g_bsum  [SCAN_NB];
__device__ int    g_boff  [SCAN_NB];
// fp16 weights
__device__ __half g_Wlh [DEPTH * DIM * HC];
__device__ __half g_Wrh [DEPTH * DIM * HC];
__device__ __half g_Wph [DEPTH * HC * DIM];
__device__ __half g_W1h [DEPTH * DIM * DMLP];
__device__ __half g_W2h [DEPTH * DMLP * DIM];

// ---------------- helpers ----------------
__device__ __forceinline__ float lrelu(float v) { return v > 0.f ? v : 0.2f * v; }

__device__ __forceinline__ uint32_t smem_u32(const void* p) {
    return (uint32_t)__cvta_generic_to_shared(p);
}

#define CP_ASYNC16(dst, src, szbytes) \
    asm volatile("cp.async.cg.shared.global [%0], [%1], 16, %2;" \
                 :: "r"(dst), "l"(src), "r"(szbytes))
#define CP_COMMIT()  asm volatile("cp.async.commit_group;")
#define CP_WAIT0()   asm volatile("cp.async.wait_group 0;")

#define LDSM4(r0, r1, r2, r3, addr) \
    asm volatile("ldmatrix.sync.aligned.m8n8.x4.shared.b16 {%0,%1,%2,%3},[%4];" \
                 : "=r"(r0), "=r"(r1), "=r"(r2), "=r"(r3) : "r"(addr))
#define LDSM4T(r0, r1, r2, r3, addr) \
    asm volatile("ldmatrix.sync.aligned.m8n8.x4.trans.shared.b16 {%0,%1,%2,%3},[%4];" \
                 : "=r"(r0), "=r"(r1), "=r"(r2), "=r"(r3) : "r"(addr))

// ---------------- fp32 -> fp16 conversion (all weights, one launch) ----------------
#define NW1 (DEPTH * DIM * HC)      // Wl
#define NW3 (DEPTH * HC * DIM)      // Wp
#define NW4 (DEPTH * DIM * DMLP)    // W1
#define NW5 (DEPTH * DMLP * DIM)    // W2
#define NWTOT (NW1 + NW1 + NW3 + NW4 + NW5)

__global__ void f2h_all_kernel(const float* __restrict__ Wl, const float* __restrict__ Wr,
                               const float* __restrict__ Wp, const float* __restrict__ W1,
                               const float* __restrict__ W2,
                               __half* __restrict__ oWl, __half* __restrict__ oWr,
                               __half* __restrict__ oWp, __half* __restrict__ oW1,
                               __half* __restrict__ oW2)
{
    int i = blockIdx.x * blockDim.x + threadIdx.x;
    int stride = gridDim.x * blockDim.x;
    for (; i < NWTOT; i += stride) {
        int j = i;
        if (j < NW1)               { oWl[j] = __float2half_rn(Wl[j]); continue; }
        j -= NW1;
        if (j < NW1)               { oWr[j] = __float2half_rn(Wr[j]); continue; }
        j -= NW1;
        if (j < NW3)               { oWp[j] = __float2half_rn(Wp[j]); continue; }
        j -= NW3;
        if (j < NW4)               { oW1[j] = __float2half_rn(W1[j]); continue; }
        j -= NW4;
        oW2[j] = __float2half_rn(W2[j]);
    }
}

// ---------------- CSR build ----------------
__global__ void hist_kernel(const int* __restrict__ dst, int* __restrict__ deg, int ne)
{
    int e = blockIdx.x * blockDim.x + threadIdx.x;
    if (e < ne) atomicAdd(&deg[dst[e]], 1);
}

// phase A: per-block inclusive scan of 1024-chunk; writes exclusive prefix (no offset) + block sum
__global__ void scan_a_kernel(const int* __restrict__ deg, int* __restrict__ rowptr,
                              int* __restrict__ bsum, int n)
{
    __shared__ int sm[SCAN_CHUNK];
    int tid = threadIdx.x;
    int i = blockIdx.x * SCAN_CHUNK + tid;
    int v = (i < n) ? deg[i] : 0;
    sm[tid] = v;
    __syncthreads();
    #pragma unroll
    for (int off = 1; off < SCAN_CHUNK; off <<= 1) {
        int t = (tid >= off) ? sm[tid - off] : 0;
        __syncthreads();
        sm[tid] += t;
        __syncthreads();
    }
    if (i < n) rowptr[i] = sm[tid] - v;            // exclusive within chunk
    if (tid == SCAN_CHUNK - 1) bsum[blockIdx.x] = sm[tid];
}

// phase B: exclusive scan of SCAN_NB block sums; writes rowptr[n] = total
__global__ void scan_b_kernel(const int* __restrict__ bsum, int* __restrict__ boff,
                              int* __restrict__ rowptr, int n)
{
    if (threadIdx.x == 0) {
        int run = 0;
        for (int b = 0; b < SCAN_NB; b++) { boff[b] = run; run += bsum[b]; }
        rowptr[n] = run;
    }
}

// phase C: add block offsets
__global__ void scan_c_kernel(int* __restrict__ rowptr, const int* __restrict__ boff, int n)
{
    int i = blockIdx.x * blockDim.x + threadIdx.x;
    if (i < n) rowptr[i] += boff[i >> 10];
}

__global__ void scatter_kernel(const int* __restrict__ src, const int* __restrict__ dst,
                               const int* __restrict__ rowptr, int* __restrict__ fill,
                               int* __restrict__ ssrc, int ne)
{
    int e = blockIdx.x * blockDim.x + threadIdx.x;
    if (e >= ne) return;
    int d = dst[e];
    int pos = rowptr[d] + atomicAdd(&fill[d], 1);
    ssrc[pos] = src[e];
}

// ---------------- standalone layernorm (layer-0 LN1 only): warp per row ----------------
__global__ void ln_kernel(const float* __restrict__ x, const float* __restrict__ g,
                          const float* __restrict__ b, __half* __restrict__ out, int n)
{
    int warp = (blockIdx.x * blockDim.x + threadIdx.x) >> 5;
    int lane = threadIdx.x & 31;
    if (warp >= n) return;
    const float4 v = ((const float4*)(x + (size_t)warp * DIM))[lane];
    float s = v.x + v.y + v.z + v.w;
    #pragma unroll
    for (int o = 16; o; o >>= 1) s += __shfl_xor_sync(~0u, s, o);
    float mu = s * (1.f / 128.f);
    float dx = v.x - mu, dy = v.y - mu, dz = v.z - mu, dw = v.w - mu;
    float q = dx*dx + dy*dy + dz*dz + dw*dw;
    #pragma unroll
    for (int o = 16; o; o >>= 1) q += __shfl_xor_sync(~0u, q, o);
    float r = rsqrtf(q * (1.f / 128.f) + 1e-5f);
    float4 gv = ((const float4*)g)[lane];
    float4 bv = ((const float4*)b)[lane];
    __half2 h0 = __floats2half2_rn(dx * r * gv.x + bv.x, dy * r * gv.y + bv.y);
    __half2 h1 = __floats2half2_rn(dz * r * gv.z + bv.z, dw * r * gv.w + bv.w);
    __half2* op = (__half2*)(out + (size_t)warp * DIM);
    op[lane * 2 + 0] = h0;
    op[lane * 2 + 1] = h1;
}

// ---------------- fp16 tensor-core GEMM mainloop ----------------
// 128x128 block tile, BK=32, 256 threads = 8 warps (2x4), warp tile 64x32, mma m16n8k16.
#define SA 40     // A smem row stride (halfs)
#define SB 136    // B smem row stride (halfs)
#define AS_HALFS (128 * SA)      // per buffer
#define BS_HALFS (32 * SB)
#define SMEM_PLAIN_BYTES (2 * AS_HALFS * 2 + 2 * BS_HALFS * 2)   // 37888
#define TSTR 132
#define SMEM_LN_BYTES (128 * TSTR * 4)                            // 67584

__device__ __forceinline__ void hgemm_mainloop(
    const __half* __restrict__ A, const __half* __restrict__ B,
    int M, int K, int Nc, int m0, int n0,
    __half* As, __half* Bs, float (&acc)[4][4][4])
{
    const int tid  = threadIdx.x;
    const int lane = tid & 31;
    const int wid  = tid >> 5;
    const int wr   = wid >> 2;
    const int wc   = wid & 3;

    #pragma unroll
    for (int i = 0; i < 4; i++)
        #pragma unroll
        for (int j = 0; j < 4; j++)
            #pragma unroll
            for (int k = 0; k < 4; k++) acc[i][j][k] = 0.f;

    const int NK = K >> 5;

    auto load_stage = [&](int buf, int kt) {
        __half* Ab = As + buf * AS_HALFS;
        __half* Bb = Bs + buf * BS_HALFS;
        #pragma unroll
        for (int i = 0; i < 2; i++) {
            int f   = tid * 2 + i;
            int row = f >> 2;
            int ch  = (f & 3) * 8;
            bool ok = (m0 + row) < M;
            const __half* src = A + (size_t)(ok ? (m0 + row) : 0) * K + kt * 32 + ch;
            CP_ASYNC16(smem_u32(&Ab[row * SA + ch]), src, ok ? 16 : 0);
        }
        #pragma unroll
        for (int i = 0; i < 2; i++) {
            int f   = tid * 2 + i;
            int row = f >> 4;
            int ch  = (f & 15) * 8;
            const __half* src = B + (size_t)(kt * 32 + row) * Nc + n0 + ch;
            CP_ASYNC16(smem_u32(&Bb[row * SB + ch]), src, 16);
        }
        CP_COMMIT();
    };

    load_stage(0, 0);
    int buf = 0;

    for (int kt = 0; kt < NK; kt++) {
        CP_WAIT0();
        __syncthreads();
        if (kt + 1 < NK) load_stage(buf ^ 1, kt + 1);
        __half* Ab = As + buf * AS_HALFS;
        __half* Bb = Bs + buf * BS_HALFS;

        #pragma unroll
        for (int ks = 0; ks < 2; ks++) {
            const int kk = ks * 16;
            uint32_t a[4][4], b[4][2];
            #pragma unroll
            for (int mt = 0; mt < 4; mt++) {
                uint32_t addr = smem_u32(
                    &Ab[(wr * 64 + mt * 16 + (lane & 15)) * SA + kk + (lane >> 4) * 8]);
                LDSM4(a[mt][0], a[mt][1], a[mt][2], a[mt][3], addr);
            }
            #pragma unroll
            for (int nh = 0; nh < 2; nh++) {
                uint32_t addr = smem_u32(
                    &Bb[(kk + (lane & 15)) * SB + wc * 32 + nh * 16 + (lane >> 4) * 8]);
                LDSM4T(b[nh * 2][0], b[nh * 2][1], b[nh * 2 + 1][0], b[nh * 2 + 1][1], addr);
            }
            #pragma unroll
            for (int mt = 0; mt < 4; mt++)
                #pragma unroll
                for (int nt = 0; nt < 4; nt++) {
                    asm volatile(
                        "mma.sync.aligned.m16n8k16.row.col.f32.f16.f16.f32 "
                        "{%0,%1,%2,%3},{%4,%5,%6,%7},{%8,%9},{%0,%1,%2,%3};"
                        : "+f"(acc[mt][nt][0]), "+f"(acc[mt][nt][1]),
                          "+f"(acc[mt][nt][2]), "+f"(acc[mt][nt][3])
                        : "r"(a[mt][0]), "r"(a[mt][1]), "r"(a[mt][2]), "r"(a[mt][3]),
                          "r"(b[nt][0]), "r"(b[nt][1]));
                }
        }
        buf ^= 1;
    }
}

// ---------------- plain GEMM kernels ----------------
// MODE 0: C = A@B + bias ; MODE 1: C = res + A@B + bias ; MODE 2: C = gelu(A@B + bias)
template<int MODE, typename OutT>
__device__ __forceinline__ void hgemm_epilogue(
    float (&acc)[4][4][4], const float* __restrict__ bias, const float* __restrict__ res,
    OutT* __restrict__ C, int M, int Nc, int m0, int n0)
{
    const int lane = threadIdx.x & 31;
    const int wid  = threadIdx.x >> 5;
    const int wr   = wid >> 2;
    const int wc   = wid & 3;
    #pragma unroll
    for (int mt = 0; mt < 4; mt++) {
        #pragma unroll
        for (int nt = 0; nt < 4; nt++) {
            int r0 = m0 + wr * 64 + mt * 16 + (lane >> 2);
            int c  = n0 + wc * 32 + nt * 8 + (lane & 3) * 2;
            float bx = bias[c], by = bias[c + 1];
            #pragma unroll
            for (int half = 0; half < 2; half++) {
                int r = r0 + half * 8;
                if (r >= M) continue;
                float vx = acc[mt][nt][half * 2 + 0] + bx;
                float vy = acc[mt][nt][half * 2 + 1] + by;
                if (MODE == 1) {
                    const float2 rv = *(const float2*)(res + (size_t)r * Nc + c);
                    vx += rv.x; vy += rv.y;
                }
                if (MODE == 2) {
                    vx = 0.5f * vx * (1.f + erff(vx * 0.70710678118654752f));
                    vy = 0.5f * vy * (1.f + erff(vy * 0.70710678118654752f));
                }
                if (sizeof(OutT) == 2) {
                    *(__half2*)((__half*)C + (size_t)r * Nc + c) = __floats2half2_rn(vx, vy);
                } else {
                    *(float2*)((float*)C + (size_t)r * Nc + c) = make_float2(vx, vy);
                }
            }
        }
    }
}

template<int MODE>
__global__ void __launch_bounds__(256) hgemm_f32_kernel(
    const __half* __restrict__ A, const __half* __restrict__ B,
    const float* __restrict__ bias, const float* __restrict__ res,
    float* __restrict__ C, int M, int K, int Nc)
{
    __shared__ __align__(16) char smraw[SMEM_PLAIN_BYTES];
    __half* As = (__half*)smraw;
    __half* Bs = (__half*)(smraw + 2 * AS_HALFS * 2);
    float acc[4][4][4];
    hgemm_mainloop(A, B, M, K, Nc, blockIdx.y * 128, blockIdx.x * 128, As, Bs, acc);
    hgemm_epilogue<MODE, float>(acc, bias, res, C, M, Nc, blockIdx.y * 128, blockIdx.x * 128);
}

template<int MODE>
__global__ void __launch_bounds__(256) hgemm_f16_kernel(
    const __half* __restrict__ A, const __half* __restrict__ B,
    const float* __restrict__ bias,
    __half* __restrict__ C, int M, int K, int Nc)
{
    __shared__ __align__(16) char smraw[SMEM_PLAIN_BYTES];
    __half* As = (__half*)smraw;
    __half* Bs = (__half*)(smraw + 2 * AS_HALFS * 2);
    float acc[4][4][4];
    hgemm_mainloop(A, B, M, K, Nc, blockIdx.y * 128, blockIdx.x * 128, As, Bs, acc);
    hgemm_epilogue<MODE, __half>(acc, bias, nullptr, C, M, Nc, blockIdx.y * 128, blockIdx.x * 128);
}

// ---------------- GEMM (Nc=128) + residual + fused LayerNorm ----------------
// C_raw = res + A@B + bias  -> xout (fp32), hout = LN(C_raw) (fp16)
// Uses dynamic smem: union of (As,Bs) and fp32 tile T[128][TSTR].
__global__ void __launch_bounds__(256) hgemm_ln_kernel(
    const __half* __restrict__ A, const __half* __restrict__ B,
    const float* __restrict__ bias, const float* __restrict__ res,
    float* __restrict__ xout, const float* __restrict__ ln_g,
    const float* __restrict__ ln_b, __half* __restrict__ hout,
    int M, int K)
{
    extern __shared__ __align__(16) char smraw[];
    __half* As = (__half*)smraw;
    __half* Bs = (__half*)(smraw + 2 * AS_HALFS * 2);
    float*  T  = (float*)smraw;

    const int m0   = blockIdx.y * 128;
    const int lane = threadIdx.x & 31;
    const int wid  = threadIdx.x >> 5;
    const int wr   = wid >> 2;
    const int wc   = wid & 3;

    float acc[4][4][4];
    hgemm_mainloop(A, B, M, K, DIM, m0, 0, As, Bs, acc);
    __syncthreads();   // all warps done with As/Bs before T overwrites them

    // write raw fp32 tile to smem
    #pragma unroll
    for (int mt = 0; mt < 4; mt++) {
        #pragma unroll
        for (int nt = 0; nt < 4; nt++) {
            int rr0 = wr * 64 + mt * 16 + (lane >> 2);
            int c   = wc * 32 + nt * 8 + (lane & 3) * 2;
            float bx = bias[c], by = bias[c + 1];
            #pragma unroll
            for (int half = 0; half < 2; half++) {
                int rr = rr0 + half * 8;
                int r  = m0 + rr;
                float vx = acc[mt][nt][half * 2 + 0] + bx;
                float vy = acc[mt][nt][half * 2 + 1] + by;
                if (r < M) {
                    const float2 rv = *(const float2*)(res + (size_t)r * DIM + c);
                    vx += rv.x; vy += rv.y;
                }
                T[rr * TSTR + c]     = vx;
                T[rr * TSTR + c + 1] = vy;
            }
        }
    }
    __syncthreads();

    // LN: warp wid handles rows [wid*16, wid*16+16)
    float4 gv = ((const float4*)ln_g)[lane];
    float4 bv = ((const float4*)ln_b)[lane];
    for (int rr = wid * 16; rr < wid * 16 + 16; rr++) {
        int r = m0 + rr;
        if (r >= M) break;
        float4 v;
        v.x = T[rr * TSTR + lane * 4 + 0];
        v.y = T[rr * TSTR + lane * 4 + 1];
        v.z = T[rr * TSTR + lane * 4 + 2];
        v.w = T[rr * TSTR + lane * 4 + 3];
        float s = v.x + v.y + v.z + v.w;
        #pragma unroll
        for (int o = 16; o; o >>= 1) s += __shfl_xor_sync(~0u, s, o);
        float mu = s * (1.f / 128.f);
        float dx = v.x - mu, dy = v.y - mu, dz = v.z - mu, dw = v.w - mu;
        float q = dx*dx + dy*dy + dz*dz + dw*dw;
        #pragma unroll
        for (int o = 16; o; o >>= 1) q += __shfl_xor_sync(~0u, q, o);
        float rs = rsqrtf(q * (1.f / 128.f) + 1e-5f);
        // write raw x
        ((float4*)(xout + (size_t)r * DIM))[lane] = v;
        // write normalized fp16 h
        __half2 h0 = __floats2half2_rn(dx * rs * gv.x + bv.x, dy * rs * gv.y + bv.y);
        __half2 h1 = __floats2half2_rn(dz * rs * gv.z + bv.z, dw * rs * gv.w + bv.w);
        __half2* op = (__half2*)(hout + (size_t)r * DIM);
        op[lane * 2 + 0] = h0;
        op[lane * 2 + 1] = h1;
    }
}

// ---------------- effective bias for Wp (both layers): bpe = bp + gat_b @ Wp ----------------
__global__ void bpe_kernel(const float* __restrict__ gat_b, const float* __restrict__ Wp,
                           const float* __restrict__ bp, float* __restrict__ out)
{
    int l = blockIdx.x;    // layer
    int j = threadIdx.x;   // 128
    const float* W = Wp + (size_t)l * HC * DIM;
    const float* gb = gat_b + l * HC;
    float s = bp[l * DIM + j];
    #pragma unroll 8
    for (int i = 0; i < HC; i++) s += gb[i] * W[(size_t)i * DIM + j];
    out[l * DIM + j] = s;
}

// ---------------- fused GATv2 edge phase: warp per dst, online softmax, depth-2 prefetch ----------------
__global__ void __launch_bounds__(256) gat_fused_kernel(
    const uint4* __restrict__ xl, const uint4* __restrict__ xr,
    const int* __restrict__ rowptr, const int* __restrict__ ssrc,
    const float* __restrict__ att, __half* __restrict__ agg, int n)
{
    int d    = (blockIdx.x * blockDim.x + threadIdx.x) >> 5;
    int lane = threadIdx.x & 31;
    if (d >= n) return;

    int beg = rowptr[d];
    int end = rowptr[d + 1];

    float rf[8], attv[8];
    {
        uint4 rv = xr[(size_t)d * 32 + lane];
        const __half2* rh = (const __half2*)&rv;
        #pragma unroll
        for (int j = 0; j < 4; j++) {
            float2 f = __half22float2(rh[j]);
            rf[2 * j] = f.x; rf[2 * j + 1] = f.y;
        }
        float4 a0 = ((const float4*)att)[lane * 2 + 0];
        float4 a1 = ((const float4*)att)[lane * 2 + 1];
        attv[0] = a0.x; attv[1] = a0.y; attv[2] = a0.z; attv[3] = a0.w;
        attv[4] = a1.x; attv[5] = a1.y; attv[6] = a1.z; attv[7] = a1.w;
    }

    float m   = -3.402823466e38f;
    float den = 0.f;
    float acc[8];
    #pragma unroll
    for (int j = 0; j < 8; j++) acc[j] = 0.f;

    // depth-2 prefetch pipeline
    uint4 pf0, pf1;
    if (beg < end)     pf0 = xl[(size_t)ssrc[beg] * 32 + lane];
    if (beg + 1 < end) pf1 = xl[(size_t)ssrc[beg + 1] * 32 + lane];

    for (int e = beg; e < end; e++) {
        uint4 cur = pf0;
        pf0 = pf1;
        if (e + 2 < end) pf1 = xl[(size_t)ssrc[e + 2] * 32 + lane];

        float lf[8];
        const __half2* lh = (const __half2*)&cur;
        #pragma unroll
        for (int j = 0; j < 4; j++) {
            float2 f = __half22float2(lh[j]);
            lf[2 * j] = f.x; lf[2 * j + 1] = f.y;
        }
        float partial = 0.f;
        #pragma unroll
        for (int j = 0; j < 8; j++)
            partial += lrelu(lf[j] + rf[j]) * attv[j];
        #pragma unroll
        for (int o = 8; o; o >>= 1) partial += __shfl_xor_sync(~0u, partial, o);
        float s = partial;

        float mnew  = fmaxf(m, s);
        float scale = __expf(m - mnew);
        float ex    = __expf(s - mnew);
        den = den * scale + ex;
        #pragma unroll
        for (int j = 0; j < 8; j++) acc[j] = acc[j] * scale + ex * lf[j];
        m = mnew;
    }

    float inv = 1.f / (den + 1e-16f);
    uint4 outp;
    __half2* oh = (__half2*)&outp;
    oh[0] = __floats2half2_rn(acc[0] * inv, acc[1] * inv);
    oh[1] = __floats2half2_rn(acc[2] * inv, acc[3] * inv);
    oh[2] = __floats2half2_rn(acc[4] * inv, acc[5] * inv);
    oh[3] = __floats2half2_rn(acc[6] * inv, acc[7] * inv);
    *(uint4*)(agg + (size_t)d * HC + lane * 8) = outp;
}

// ---------------- host ----------------
extern "C" void kernel_launch(void* const* d_in, const int* in_sizes, int n_in,
                              void* d_out, int out_size)
{
    const float* x     = (const float*)d_in[0];
    const int*   ei    = (const int*)  d_in[1];
    const float* ln1_g = (const float*)d_in[2];
    const float* ln1_b = (const float*)d_in[3];
    const float* Wl    = (const float*)d_in[4];
    const float* bl    = (const float*)d_in[5];
    const float* Wr    = (const float*)d_in[6];
    const float* br    = (const float*)d_in[7];
    const float* att   = (const float*)d_in[8];
    const float* gat_b = (const float*)d_in[9];
    const float* Wp    = (const float*)d_in[10];
    const float* bp    = (const float*)d_in[11];
    const float* ln2_g = (const float*)d_in[12];
    const float* ln2_b = (const float*)d_in[13];
    const float* W1    = (const float*)d_in[14];
    const float* b1    = (const float*)d_in[15];
    const float* W2    = (const float*)d_in[16];
    const float* b2    = (const float*)d_in[17];

    const int n  = NN;
    const int ne = EE;
    const int* src = ei;
    const int* dst = ei + ne;

    float *gx, *gbpe;
    __half *ghh, *gxlh, *gxrh, *gaggh, *gmlph;
    __half *gWlh, *gWrh, *gWph, *gW1h, *gW2h;
    int *gdeg, *growptr, *gfill, *gssrc, *gbsum, *gboff;
    cudaGetSymbolAddress((void**)&gx,     g_x);
    cudaGetSymbolAddress((void**)&ghh,    g_hh);
    cudaGetSymbolAddress((void**)&gxlh,   g_xlh);
    cudaGetSymbolAddress((void**)&gxrh,   g_xrh);
    cudaGetSymbolAddress((void**)&gaggh,  g_aggh);
    cudaGetSymbolAddress((void**)&gmlph,  g_mlph);
    cudaGetSymbolAddress((void**)&gbpe,   g_bpe);
    cudaGetSymbolAddress((void**)&gdeg,   g_deg);
    cudaGetSymbolAddress((void**)&growptr,g_rowptr);
    cudaGetSymbolAddress((void**)&gfill,  g_fill);
    cudaGetSymbolAddress((void**)&gssrc,  g_ssrc);
    cudaGetSymbolAddress((void**)&gbsum,  g_bsum);
    cudaGetSymbolAddress((void**)&gboff,  g_boff);
    cudaGetSymbolAddress((void**)&gWlh,   g_Wlh);
    cudaGetSymbolAddress((void**)&gWrh,   g_Wrh);
    cudaGetSymbolAddress((void**)&gWph,   g_Wph);
    cudaGetSymbolAddress((void**)&gW1h,   g_W1h);
    cudaGetSymbolAddress((void**)&gW2h,   g_W2h);

    cudaFuncSetAttribute(hgemm_ln_kernel,
                         cudaFuncAttributeMaxDynamicSharedMemorySize, SMEM_LN_BYTES);

    // ---- preludes ----
    f2h_all_kernel<<<448, 256>>>(Wl, Wr, Wp, W1, W2, gWlh, gWrh, gWph, gW1h, gW2h);
    bpe_kernel<<<2, DIM>>>(gat_b, Wp, bp, gbpe);

    cudaMemsetAsync(gdeg,  0, sizeof(int) * n);
    cudaMemsetAsync(gfill, 0, sizeof(int) * n);
    hist_kernel<<<(ne + 255) / 256, 256>>>(dst, gdeg, ne);
    scan_a_kernel<<<SCAN_NB, SCAN_CHUNK>>>(gdeg, growptr, gbsum, n);
    scan_b_kernel<<<1, 32>>>(gbsum, gboff, growptr, n);
    scan_c_kernel<<<(n + 255) / 256, 256>>>(growptr, gboff, n);
    scatter_kernel<<<(ne + 255) / 256, 256>>>(src, dst, growptr, gfill, gssrc, ne);

    // layer-0 LN1 directly from input
    ln_kernel<<<(n + 7) / 8, 256>>>(x, ln1_g, ln1_b, ghh, n);

    const int gatBlocks = (n + 7) / 8;
    const int mBlocks   = (n + 127) / 128;   // 391

    for (int l = 0; l < 2; l++) {
        const float* resx = (l == 0) ? x : gx;   // residual input to Wp GEMM

        hgemm_f16_kernel<0><<<dim3(HC / 128, mBlocks), 256>>>(
            ghh, gWlh + (size_t)l * DIM * HC, bl + l * HC, gxlh, n, DIM, HC);
        hgemm_f16_kernel<0><<<dim3(HC / 128, mBlocks), 256>>>(
            ghh, gWrh + (size_t)l * DIM * HC, br + l * HC, gxrh, n, DIM, HC);

        gat_fused_kernel<<<gatBlocks, 256>>>((const uint4*)gxlh, (const uint4*)gxrh,
                                             growptr, gssrc, att + l * HC, gaggh, n);

        // x = resx + agg@Wp + bpe ; h = LN2(x)
        hgemm_ln_kernel<<<dim3(1, mBlocks), 256, SMEM_LN_BYTES>>>(
            gaggh, gWph + (size_t)l * HC * DIM, gbpe + l * DIM, resx,
            gx, ln2_g + l * DIM, ln2_b + l * DIM, ghh, n, HC);

        hgemm_f16_kernel<2><<<dim3(DMLP / 128, mBlocks), 256>>>(
            ghh, gW1h + (size_t)l * DIM * DMLP, b1 + l * DMLP, gmlph, n, DIM, DMLP);

        if (l == 0) {
            // x = x + mlp@W2 + b2 ; h = LN1_layer1(x)
            hgemm_ln_kernel<<<dim3(1, mBlocks), 256, SMEM_LN_BYTES>>>(
                gmlph, gW2h, b2, gx,
                gx, ln1_g + DIM, ln1_b + DIM, ghh, n, DMLP);
        } else {
            // final: write d_out directly
            hgemm_f32_kernel<1><<<dim3(1, mBlocks), 256>>>(
                gmlph, gW2h + (size_t)DMLP * DIM, b2 + DIM, gx,
                (float*)d_out, n, DMLP, DIM);
        }
    }
}